// round 1
// baseline (speedup 1.0000x reference)
#include <cuda_runtime.h>
#include <math.h>

#define N_HEAD   16
#define HEAD_DIM 64
#define EMBD     1024
#define BATCH    2
#define SEQ      2048
#define M_TOTAL  (BATCH*SEQ)   // 4096

// Scratch (allocation-free rule: device globals)
__device__ float g_q[(size_t)BATCH*N_HEAD*SEQ*HEAD_DIM];   // 16 MB, [B,H,S,D]
__device__ float g_attn[(size_t)M_TOTAL*EMBD];             // 16 MB, [B*S, E]

// ---------------- GEMM: C = A[4096,1024] @ B[1024,ldb] + bias ----------------
#define BM 128
#define BN 64
#define BK 16

__global__ __launch_bounds__(256)
void gemm_kernel(const float* __restrict__ A, const float* __restrict__ B,
                 const float* __restrict__ bias, int ldb, int mode,
                 float* __restrict__ o_q, float* __restrict__ o_k,
                 float* __restrict__ o_v)
{
    __shared__ float As[BK][BM+4];   // k-major (transposed store)
    __shared__ float Bs[BK][BN+4];

    const int tid = threadIdx.x;
    const int tx = tid & 15, ty = tid >> 4;
    const int m0 = blockIdx.y * BM, n0 = blockIdx.x * BN;

    float acc[8][4];
#pragma unroll
    for (int i = 0; i < 8; i++)
#pragma unroll
        for (int j = 0; j < 4; j++) acc[i][j] = 0.f;

    for (int kt = 0; kt < EMBD; kt += BK) {
        // A tile: 128x16 = 512 float4, 2 per thread, transpose into As
#pragma unroll
        for (int s = 0; s < 2; s++) {
            int idx = tid + s * 256;
            int row = idx >> 2, c4 = (idx & 3) * 4;
            float4 a = *(const float4*)(A + (size_t)(m0 + row) * EMBD + kt + c4);
            As[c4 + 0][row] = a.x; As[c4 + 1][row] = a.y;
            As[c4 + 2][row] = a.z; As[c4 + 3][row] = a.w;
        }
        // B tile: 16x64 = 256 float4, 1 per thread
        {
            int r = tid >> 4, c4 = (tid & 15) * 4;
            float4 b = *(const float4*)(B + (size_t)(kt + r) * ldb + n0 + c4);
            *(float4*)&Bs[r][c4] = b;
        }
        __syncthreads();
#pragma unroll
        for (int kk = 0; kk < BK; kk++) {
            float4 a0 = *(float4*)&As[kk][ty * 8];
            float4 a1 = *(float4*)&As[kk][ty * 8 + 4];
            float4 b0 = *(float4*)&Bs[kk][tx * 4];
            float a[8] = {a0.x, a0.y, a0.z, a0.w, a1.x, a1.y, a1.z, a1.w};
            float b[4] = {b0.x, b0.y, b0.z, b0.w};
#pragma unroll
            for (int i = 0; i < 8; i++)
#pragma unroll
                for (int j = 0; j < 4; j++)
                    acc[i][j] += a[i] * b[j];
        }
        __syncthreads();
    }

    float bb[4];
#pragma unroll
    for (int j = 0; j < 4; j++) bb[j] = bias[n0 + tx * 4 + j];

    if (mode == 0) {
        // QKV epilogue: scatter into [B,H,S,D]. sec/h are uniform per block.
        int sec = n0 >> 10;
        int h   = (n0 & 1023) >> 6;
        float* dst = (sec == 0) ? o_q : (sec == 1) ? o_k : o_v;
#pragma unroll
        for (int i = 0; i < 8; i++) {
            int m = m0 + ty * 8 + i;
            int b = m >> 11, s = m & 2047;
            float4 v4;
            v4.x = acc[i][0] + bb[0];
            v4.y = acc[i][1] + bb[1];
            v4.z = acc[i][2] + bb[2];
            v4.w = acc[i][3] + bb[3];
            size_t idx = (((size_t)(b * N_HEAD + h) * SEQ + s) * HEAD_DIM) + tx * 4;
            *(float4*)(dst + idx) = v4;
        }
    } else {
        // Proj epilogue: row-major [4096, 1024]
#pragma unroll
        for (int i = 0; i < 8; i++) {
            int m = m0 + ty * 8 + i;
            float4 v4;
            v4.x = acc[i][0] + bb[0];
            v4.y = acc[i][1] + bb[1];
            v4.z = acc[i][2] + bb[2];
            v4.w = acc[i][3] + bb[3];
            *(float4*)(o_q + (size_t)m * EMBD + n0 + tx * 4) = v4;
        }
    }
}

// ---------------- Flash attention: per (b,h), causal, 64-row q tiles --------
#define SSTR 68   // smem row stride (conflict-free padding)

__global__ __launch_bounds__(256)
void flash_kernel(const float* __restrict__ q, const float* __restrict__ k,
                  const float* __restrict__ v, float* __restrict__ out)
{
    extern __shared__ float sm[];
    float* Qs = sm;                 // [r][d]
    float* Ks = sm + 64 * SSTR;     // [d][c]  (transposed)
    float* Vs = sm + 2 * 64 * SSTR; // [c][d]
    float* Ps = sm + 3 * 64 * SSTR; // [r][c]

    const int tid = threadIdx.x;
    const int tx = tid & 15, ty = tid >> 4;
    const int qt = blockIdx.x, bh = blockIdx.y;
    const size_t base = (size_t)bh * SEQ * HEAD_DIM;
    const int q0 = qt * 64;

    // Load Q tile (pre-scaled by 1/sqrt(64))
#pragma unroll
    for (int s2 = 0; s2 < 4; s2++) {
        int idx = tid + s2 * 256;
        int row = idx >> 4, c4 = (idx & 15) * 4;
        float4 qv = *(const float4*)(q + base + (size_t)(q0 + row) * HEAD_DIM + c4);
        qv.x *= 0.125f; qv.y *= 0.125f; qv.z *= 0.125f; qv.w *= 0.125f;
        *(float4*)&Qs[row * SSTR + c4] = qv;
    }

    float m[4], l[4], o[4][4];
#pragma unroll
    for (int i = 0; i < 4; i++) {
        m[i] = -1e30f; l[i] = 0.f;
#pragma unroll
        for (int j = 0; j < 4; j++) o[i][j] = 0.f;
    }

    for (int jt = 0; jt <= qt; jt++) {
        __syncthreads();   // protect K/V/P from previous iteration's readers
        // Load K (transposed to [d][c]) and V tiles
#pragma unroll
        for (int s2 = 0; s2 < 4; s2++) {
            int idx = tid + s2 * 256;
            int c = idx >> 4, d4 = (idx & 15) * 4;
            float4 kv = *(const float4*)(k + base + (size_t)(jt * 64 + c) * HEAD_DIM + d4);
            Ks[(d4 + 0) * SSTR + c] = kv.x;
            Ks[(d4 + 1) * SSTR + c] = kv.y;
            Ks[(d4 + 2) * SSTR + c] = kv.z;
            Ks[(d4 + 3) * SSTR + c] = kv.w;
            float4 vv = *(const float4*)(v + base + (size_t)(jt * 64 + c) * HEAD_DIM + d4);
            *(float4*)&Vs[c * SSTR + d4] = vv;
        }
        __syncthreads();

        // S = Q K^T : thread owns rows ty*4+i, cols tx+16*j
        float p[4][4];
#pragma unroll
        for (int i = 0; i < 4; i++)
#pragma unroll
            for (int j = 0; j < 4; j++) p[i][j] = 0.f;
        for (int kk = 0; kk < 64; kk++) {
            float qr[4], kc[4];
#pragma unroll
            for (int i = 0; i < 4; i++) qr[i] = Qs[(ty * 4 + i) * SSTR + kk];
#pragma unroll
            for (int j = 0; j < 4; j++) kc[j] = Ks[kk * SSTR + tx + 16 * j];
#pragma unroll
            for (int i = 0; i < 4; i++)
#pragma unroll
                for (int j = 0; j < 4; j++)
                    p[i][j] += qr[i] * kc[j];
        }
        if (jt == qt) {   // diagonal tile: causal mask (local indices suffice)
#pragma unroll
            for (int i = 0; i < 4; i++)
#pragma unroll
                for (int j = 0; j < 4; j++)
                    if (tx + 16 * j > ty * 4 + i) p[i][j] = -1e30f;
        }

        // Online softmax (row spans the 16 tx lanes of a warp half)
#pragma unroll
        for (int i = 0; i < 4; i++) {
            float mx = p[i][0];
#pragma unroll
            for (int j = 1; j < 4; j++) mx = fmaxf(mx, p[i][j]);
#pragma unroll
            for (int off = 1; off < 16; off <<= 1)
                mx = fmaxf(mx, __shfl_xor_sync(0xffffffffu, mx, off));
            float mn = fmaxf(m[i], mx);
            float alpha = __expf(m[i] - mn);
            m[i] = mn;
            float rs = 0.f;
#pragma unroll
            for (int j = 0; j < 4; j++) {
                p[i][j] = __expf(p[i][j] - mn);
                rs += p[i][j];
            }
#pragma unroll
            for (int off = 1; off < 16; off <<= 1)
                rs += __shfl_xor_sync(0xffffffffu, rs, off);
            l[i] = l[i] * alpha + rs;
#pragma unroll
            for (int j = 0; j < 4; j++) o[i][j] *= alpha;
        }

        __syncthreads();
#pragma unroll
        for (int i = 0; i < 4; i++)
#pragma unroll
            for (int j = 0; j < 4; j++)
                Ps[(ty * 4 + i) * SSTR + tx + 16 * j] = p[i][j];
        __syncthreads();

        // O += P V : thread owns rows ty*4+i, D-cols tx+16*j
        for (int c = 0; c < 64; c++) {
            float pv[4], vv[4];
#pragma unroll
            for (int i = 0; i < 4; i++) pv[i] = Ps[(ty * 4 + i) * SSTR + c];
#pragma unroll
            for (int j = 0; j < 4; j++) vv[j] = Vs[c * SSTR + tx + 16 * j];
#pragma unroll
            for (int i = 0; i < 4; i++)
#pragma unroll
                for (int j = 0; j < 4; j++)
                    o[i][j] += pv[i] * vv[j];
        }
    }

    // Write to [B, S, H*D] scratch (row-major [4096, 1024] for proj GEMM)
    int b = bh >> 4, h = bh & 15;
#pragma unroll
    for (int i = 0; i < 4; i++) {
        float inv = 1.f / l[i];
        int gr = q0 + ty * 4 + i;
#pragma unroll
        for (int j = 0; j < 4; j++)
            out[(size_t)(b * SEQ + gr) * EMBD + h * HEAD_DIM + tx + 16 * j]
                = o[i][j] * inv;
    }
}

// ---------------------------------------------------------------------------
extern "C" void kernel_launch(void* const* d_in, const int* in_sizes, int n_in,
                              void* d_out, int out_size)
{
    const float* x      = (const float*)d_in[0];
    const float* qkv_w  = (const float*)d_in[1];
    const float* qkv_b  = (const float*)d_in[2];
    const float* proj_w = (const float*)d_in[3];
    const float* proj_b = (const float*)d_in[4];

    float* out  = (float*)d_out;                          // [B,S,E]
    float* outK = out  + (size_t)BATCH * SEQ * EMBD;      // [B,H,S,D]
    float* outV = outK + (size_t)BATCH * SEQ * EMBD;      // [B,H,S,D]

    float* qbuf = nullptr;
    float* abuf = nullptr;
    cudaGetSymbolAddress((void**)&qbuf, g_q);
    cudaGetSymbolAddress((void**)&abuf, g_attn);

    const int flash_smem = 4 * 64 * SSTR * (int)sizeof(float);  // 69632
    cudaFuncSetAttribute(flash_kernel,
                         cudaFuncAttributeMaxDynamicSharedMemorySize, flash_smem);

    // 1) QKV GEMM + bias, scatter K/V straight into d_out, Q into scratch
    gemm_kernel<<<dim3(3 * EMBD / BN, M_TOTAL / BM), 256>>>(
        x, qkv_w, qkv_b, 3 * EMBD, 0, qbuf, outK, outV);

    // 2) Causal flash attention over 32 (b,h) pairs x 32 q-tiles
    flash_kernel<<<dim3(SEQ / 64, BATCH * N_HEAD), 256, flash_smem>>>(
        qbuf, outK, outV, abuf);

    // 3) Output projection + bias
    gemm_kernel<<<dim3(EMBD / BN, M_TOTAL / BM), 256>>>(
        abuf, proj_w, proj_b, EMBD, 1, out, nullptr, nullptr);
}

// round 3
// speedup vs baseline: 2.9396x; 2.9396x over previous
#include <cuda_runtime.h>
#include <math.h>
#include <stdint.h>

#define N_HEAD   16
#define HEAD_DIM 64
#define EMBD     1024
#define BATCH    2
#define SEQ      2048
#define M_TOTAL  (BATCH*SEQ)   // 4096

// ---------------- scratch (device globals; no allocs allowed) ---------------
__device__ float g_q[(size_t)BATCH*N_HEAD*SEQ*HEAD_DIM];     // Q [B,H,S,D], tf32-rounded
__device__ float g_attn[(size_t)M_TOTAL*EMBD];               // attn out [B*S,E], rounded
__device__ float g_xr[(size_t)M_TOTAL*EMBD];                 // x rounded to tf32
__device__ float g_wt_qkv[(size_t)3*EMBD*EMBD];              // W_qkv^T [3072,1024], rounded
__device__ float g_wt_proj[(size_t)EMBD*EMBD];               // W_proj^T [1024,1024], rounded

// ---------------- helpers ---------------------------------------------------
__device__ __forceinline__ uint32_t smem_u32(const void* p) {
    uint32_t a;
    asm("{ .reg .u64 t; cvta.to.shared.u64 t, %1; cvt.u32.u64 %0, t; }" : "=r"(a) : "l"(p));
    return a;
}
__device__ __forceinline__ float tf32_rna(float x) {
    uint32_t u;
    asm("cvt.rna.tf32.f32 %0, %1;" : "=r"(u) : "f"(x));
    return __uint_as_float(u);
}
// D += A(16x8,row) * B(8x8,col), tf32 inputs in fp32 containers (pre-rounded RNA)
__device__ __forceinline__ void mma_tf32(float* c, const float* a, const float* b) {
    asm volatile("mma.sync.aligned.m16n8k8.row.col.f32.tf32.tf32.f32 "
        "{%0,%1,%2,%3}, {%4,%5,%6,%7}, {%8,%9}, {%0,%1,%2,%3};"
        : "+f"(c[0]), "+f"(c[1]), "+f"(c[2]), "+f"(c[3])
        : "r"(__float_as_uint(a[0])), "r"(__float_as_uint(a[1])),
          "r"(__float_as_uint(a[2])), "r"(__float_as_uint(a[3])),
          "r"(__float_as_uint(b[0])), "r"(__float_as_uint(b[1])));
}
__device__ __forceinline__ void cp16(void* dst_smem, const void* src) {
    uint32_t d = smem_u32(dst_smem);
    asm volatile("cp.async.cg.shared.global [%0], [%1], 16;" :: "r"(d), "l"(src) : "memory");
}
#define CP_COMMIT() asm volatile("cp.async.commit_group;" ::: "memory")
#define CP_WAIT(n)  asm volatile("cp.async.wait_group %0;" :: "n"(n) : "memory")

// ---------------- prep kernels ----------------------------------------------
__global__ __launch_bounds__(256)
void transpose_tf32_kernel(const float* __restrict__ W, float* __restrict__ WT, int N)
{
    __shared__ float t[32][33];
    int n0 = blockIdx.x * 32, k0 = blockIdx.y * 32;
    int tx = threadIdx.x, ty = threadIdx.y;
#pragma unroll
    for (int i = 0; i < 4; i++)
        t[ty + 8 * i][tx] = W[(size_t)(k0 + ty + 8 * i) * N + n0 + tx];
    __syncthreads();
#pragma unroll
    for (int i = 0; i < 4; i++)
        WT[(size_t)(n0 + ty + 8 * i) * EMBD + k0 + tx] = tf32_rna(t[tx][ty + 8 * i]);
}

__global__ __launch_bounds__(256)
void round_tf32_kernel(const float* __restrict__ x, float* __restrict__ y, int n4)
{
    int i = blockIdx.x * blockDim.x + threadIdx.x;
    if (i < n4) {
        float4 v = ((const float4*)x)[i];
        v.x = tf32_rna(v.x); v.y = tf32_rna(v.y);
        v.z = tf32_rna(v.z); v.w = tf32_rna(v.w);
        ((float4*)y)[i] = v;
    }
}

// ---------------- tf32 mma.sync GEMM ---------------------------------------
// C[M,Ntot] = A[M,1024] @ Bt^T + bias.  A row-major K-contig; Bt [Ntot,1024] K-contig.
// Block 128x128, BK=32, 2-stage cp.async. 8 warps, each 32(M)x64(N).
#define GPAD 36
#define GKT  (EMBD/32)

__global__ __launch_bounds__(256)
void gemm_tc(const float* __restrict__ A, const float* __restrict__ Bt,
             const float* __restrict__ bias, int mode,
             float* __restrict__ o0, float* __restrict__ o1, float* __restrict__ o2)
{
    extern __shared__ float smg[];
    float* SA = smg;                       // [2][128*GPAD]
    float* SB = smg + 2 * 128 * GPAD;      // [2][128*GPAD]

    const int tid = threadIdx.x, wid = tid >> 5, lane = tid & 31;
    const int g = lane >> 2, t4 = lane & 3;
    const int wm = wid >> 1, wn = wid & 1;
    const int m0 = blockIdx.y * 128, n0 = blockIdx.x * 128;
    const float* Ab = A  + (size_t)m0 * EMBD;
    const float* Bb = Bt + (size_t)n0 * EMBD;

    float c[2][8][4];
#pragma unroll
    for (int mt = 0; mt < 2; mt++)
#pragma unroll
        for (int nt = 0; nt < 8; nt++)
#pragma unroll
            for (int e = 0; e < 4; e++) c[mt][nt][e] = 0.f;

    auto load_tile = [&](int t) {
        float* as = SA + (t & 1) * 128 * GPAD;
        float* bs = SB + (t & 1) * 128 * GPAD;
        int kt = t * 32;
#pragma unroll
        for (int i = 0; i < 4; i++) {
            int idx = tid + i * 256;
            int r = idx >> 3, ch = idx & 7;
            cp16(as + r * GPAD + ch * 4, Ab + (size_t)r * EMBD + kt + ch * 4);
        }
#pragma unroll
        for (int i = 0; i < 4; i++) {
            int idx = tid + i * 256;
            int r = idx >> 3, ch = idx & 7;
            cp16(bs + r * GPAD + ch * 4, Bb + (size_t)r * EMBD + kt + ch * 4);
        }
    };

    load_tile(0); CP_COMMIT();

    for (int t = 0; t < GKT; t++) {
        if (t + 1 < GKT) { load_tile(t + 1); CP_COMMIT(); CP_WAIT(1); }
        else             { CP_WAIT(0); }
        __syncthreads();
        const float* as = SA + (t & 1) * 128 * GPAD;
        const float* bs = SB + (t & 1) * 128 * GPAD;
#pragma unroll
        for (int k8 = 0; k8 < 4; k8++) {
            int k0 = k8 * 8;
            float a[2][4], b[8][2];
#pragma unroll
            for (int mt = 0; mt < 2; mt++) {
                int rb = wm * 32 + mt * 16;
                a[mt][0] = as[(rb + g)     * GPAD + k0 + t4];
                a[mt][1] = as[(rb + 8 + g) * GPAD + k0 + t4];
                a[mt][2] = as[(rb + g)     * GPAD + k0 + 4 + t4];
                a[mt][3] = as[(rb + 8 + g) * GPAD + k0 + 4 + t4];
            }
#pragma unroll
            for (int nt = 0; nt < 8; nt++) {
                int cb = wn * 64 + nt * 8;
                b[nt][0] = bs[(cb + g) * GPAD + k0 + t4];
                b[nt][1] = bs[(cb + g) * GPAD + k0 + 4 + t4];
            }
#pragma unroll
            for (int mt = 0; mt < 2; mt++)
#pragma unroll
                for (int nt = 0; nt < 8; nt++)
                    mma_tf32(c[mt][nt], a[mt], b[nt]);
        }
        __syncthreads();
    }

    // epilogue
#pragma unroll
    for (int mt = 0; mt < 2; mt++) {
#pragma unroll
        for (int nt = 0; nt < 8; nt++) {
            int row0 = m0 + wm * 32 + mt * 16 + g;
            int row1 = row0 + 8;
            int col  = n0 + wn * 64 + nt * 8 + 2 * t4;
            float b0 = bias[col], b1 = bias[col + 1];
            float2 v0 = make_float2(c[mt][nt][0] + b0, c[mt][nt][1] + b1);
            float2 v1 = make_float2(c[mt][nt][2] + b0, c[mt][nt][3] + b1);
            if (mode == 0) {
                // Q/K/V are future MMA operands: RNA-round now
                v0.x = tf32_rna(v0.x); v0.y = tf32_rna(v0.y);
                v1.x = tf32_rna(v1.x); v1.y = tf32_rna(v1.y);
                int sec = col >> 10, nn = col & 1023;
                int h = nn >> 6, d = nn & 63;
                float* dst = (sec == 0) ? o0 : (sec == 1) ? o1 : o2;
                int b_0 = row0 >> 11, s_0 = row0 & 2047;
                int b_1 = row1 >> 11, s_1 = row1 & 2047;
                *(float2*)&dst[(((size_t)(b_0 * N_HEAD + h) * SEQ + s_0) << 6) + d] = v0;
                *(float2*)&dst[(((size_t)(b_1 * N_HEAD + h) * SEQ + s_1) << 6) + d] = v1;
            } else {
                *(float2*)&o0[(size_t)row0 * EMBD + col] = v0;
                *(float2*)&o0[(size_t)row1 * EMBD + col] = v1;
            }
        }
    }
}

// ---------------- flash attention with tf32 mma.sync ------------------------
// Block: 128 queries x one (b,h); 8 warps, warp = 16 rows x full 64 cols.
#define FSTR 68

__global__ __launch_bounds__(256)
void flash_tc(const float* __restrict__ q, const float* __restrict__ k,
              const float* __restrict__ v, float* __restrict__ out)
{
    extern __shared__ float smf[];
    float* Qs = smf;                    // [128][FSTR]
    float* Ks = smf + 128 * FSTR;       // [2][64][FSTR]
    float* Vs = Ks + 2 * 64 * FSTR;     // [2][64][FSTR]
    float* Ps = Vs + 2 * 64 * FSTR;     // [128][FSTR] (warp-private rows)

    const int tid = threadIdx.x, wid = tid >> 5, lane = tid & 31;
    const int g = lane >> 2, t4 = lane & 3;
    const int qb = blockIdx.x, bh = blockIdx.y;
    const int q0 = qb * 128;
    const size_t base = (size_t)bh * SEQ * HEAD_DIM;
    const int qw = q0 + wid * 16;       // warp's first query row
    const int jtmax = 2 * qb + 1;

    auto load_kv = [&](int jt) {
        float* kd = Ks + (jt & 1) * 64 * FSTR;
        float* vd = Vs + (jt & 1) * 64 * FSTR;
        const float* kg = k + base + (size_t)jt * 64 * 64;
        const float* vg = v + base + (size_t)jt * 64 * 64;
#pragma unroll
        for (int i = 0; i < 4; i++) {
            int idx = tid + i * 256;
            int r = idx >> 4, ch = idx & 15;
            cp16(kd + r * FSTR + ch * 4, kg + (size_t)r * 64 + ch * 4);
            cp16(vd + r * FSTR + ch * 4, vg + (size_t)r * 64 + ch * 4);
        }
    };

    // Q tile (already tf32-rounded by QKV epilogue) + first KV tile
#pragma unroll
    for (int i = 0; i < 8; i++) {
        int idx = tid + i * 256;
        int r = idx >> 4, ch = idx & 15;
        cp16(Qs + r * FSTR + ch * 4, q + base + (size_t)(q0 + r) * 64 + ch * 4);
    }
    load_kv(0);
    CP_COMMIT();

    float mr[2] = {-1e30f, -1e30f}, lr[2] = {0.f, 0.f};
    float o[8][4];
#pragma unroll
    for (int nt = 0; nt < 8; nt++)
#pragma unroll
        for (int e = 0; e < 4; e++) o[nt][e] = 0.f;

    for (int jt = 0; jt <= jtmax; jt++) {
        if (jt < jtmax) { load_kv(jt + 1); CP_COMMIT(); CP_WAIT(1); }
        else            { CP_WAIT(0); }
        __syncthreads();
        const float* Kb = Ks + (jt & 1) * 64 * FSTR;
        const float* Vb = Vs + (jt & 1) * 64 * FSTR;

        if (jt * 64 <= qw + 15) {       // warp has at least one unmasked element
            // ---- S = Q K^T (16x64) ----
            float s[8][4];
#pragma unroll
            for (int nt = 0; nt < 8; nt++)
#pragma unroll
                for (int e = 0; e < 4; e++) s[nt][e] = 0.f;
#pragma unroll
            for (int k8 = 0; k8 < 8; k8++) {
                int k0 = k8 * 8;
                float aq[4];
                aq[0] = Qs[(wid * 16 + g)     * FSTR + k0 + t4];
                aq[1] = Qs[(wid * 16 + 8 + g) * FSTR + k0 + t4];
                aq[2] = Qs[(wid * 16 + g)     * FSTR + k0 + 4 + t4];
                aq[3] = Qs[(wid * 16 + 8 + g) * FSTR + k0 + 4 + t4];
#pragma unroll
                for (int nt = 0; nt < 8; nt++) {
                    float bk[2];
                    bk[0] = Kb[(nt * 8 + g) * FSTR + k0 + t4];
                    bk[1] = Kb[(nt * 8 + g) * FSTR + k0 + 4 + t4];
                    mma_tf32(s[nt], aq, bk);
                }
            }
            // ---- scale + causal mask ----
            bool diag = (jt * 64 + 63 > qw);
#pragma unroll
            for (int nt = 0; nt < 8; nt++) {
                int colb = jt * 64 + nt * 8 + 2 * t4;
#pragma unroll
                for (int e = 0; e < 4; e++) {
                    int row = qw + g + (e >> 1) * 8;
                    int col = colb + (e & 1);
                    s[nt][e] *= 0.125f;
                    if (diag && col > row) s[nt][e] = -1e30f;
                }
            }
            // ---- online softmax (rows live in a quad: shfl over lanes 1,2) ----
            float mx0 = -1e30f, mx1 = -1e30f;
#pragma unroll
            for (int nt = 0; nt < 8; nt++) {
                mx0 = fmaxf(mx0, fmaxf(s[nt][0], s[nt][1]));
                mx1 = fmaxf(mx1, fmaxf(s[nt][2], s[nt][3]));
            }
            mx0 = fmaxf(mx0, __shfl_xor_sync(0xffffffffu, mx0, 1));
            mx0 = fmaxf(mx0, __shfl_xor_sync(0xffffffffu, mx0, 2));
            mx1 = fmaxf(mx1, __shfl_xor_sync(0xffffffffu, mx1, 1));
            mx1 = fmaxf(mx1, __shfl_xor_sync(0xffffffffu, mx1, 2));
            float mn0 = fmaxf(mr[0], mx0), mn1 = fmaxf(mr[1], mx1);
            float al0 = __expf(mr[0] - mn0), al1 = __expf(mr[1] - mn1);
            mr[0] = mn0; mr[1] = mn1;
            float sum0 = 0.f, sum1 = 0.f;
#pragma unroll
            for (int nt = 0; nt < 8; nt++) {
                s[nt][0] = __expf(s[nt][0] - mn0); sum0 += s[nt][0];
                s[nt][1] = __expf(s[nt][1] - mn0); sum0 += s[nt][1];
                s[nt][2] = __expf(s[nt][2] - mn1); sum1 += s[nt][2];
                s[nt][3] = __expf(s[nt][3] - mn1); sum1 += s[nt][3];
            }
            sum0 += __shfl_xor_sync(0xffffffffu, sum0, 1);
            sum0 += __shfl_xor_sync(0xffffffffu, sum0, 2);
            sum1 += __shfl_xor_sync(0xffffffffu, sum1, 1);
            sum1 += __shfl_xor_sync(0xffffffffu, sum1, 2);
            lr[0] = lr[0] * al0 + sum0;
            lr[1] = lr[1] * al1 + sum1;
#pragma unroll
            for (int nt = 0; nt < 8; nt++) {
                o[nt][0] *= al0; o[nt][1] *= al0;
                o[nt][2] *= al1; o[nt][3] *= al1;
            }
            // ---- P -> warp-private smem (RNA-rounded), C-frag -> A-frag fixup ----
#pragma unroll
            for (int nt = 0; nt < 8; nt++) {
                float2 p0 = make_float2(tf32_rna(s[nt][0]), tf32_rna(s[nt][1]));
                float2 p1 = make_float2(tf32_rna(s[nt][2]), tf32_rna(s[nt][3]));
                *(float2*)&Ps[(wid * 16 + g)     * FSTR + nt * 8 + 2 * t4] = p0;
                *(float2*)&Ps[(wid * 16 + 8 + g) * FSTR + nt * 8 + 2 * t4] = p1;
            }
            __syncwarp();
            // ---- O += P V ----
#pragma unroll
            for (int k8 = 0; k8 < 8; k8++) {
                int k0 = k8 * 8;
                float ap[4];
                ap[0] = Ps[(wid * 16 + g)     * FSTR + k0 + t4];
                ap[1] = Ps[(wid * 16 + 8 + g) * FSTR + k0 + t4];
                ap[2] = Ps[(wid * 16 + g)     * FSTR + k0 + 4 + t4];
                ap[3] = Ps[(wid * 16 + 8 + g) * FSTR + k0 + 4 + t4];
#pragma unroll
                for (int nt = 0; nt < 8; nt++) {
                    float bv[2];
                    bv[0] = Vb[(k0 + t4)     * FSTR + nt * 8 + g];
                    bv[1] = Vb[(k0 + 4 + t4) * FSTR + nt * 8 + g];
                    mma_tf32(o[nt], ap, bv);
                }
            }
        }
        __syncthreads();
    }

    // ---- normalize + store (RNA-rounded: A operand of proj GEMM) ----
    int b_ = bh >> 4, h = bh & 15;
    float i0 = 1.f / lr[0], i1 = 1.f / lr[1];
#pragma unroll
    for (int nt = 0; nt < 8; nt++) {
        int d = nt * 8 + 2 * t4;
        int r0 = qw + g, r1 = qw + 8 + g;
        float2 v0 = make_float2(tf32_rna(o[nt][0] * i0), tf32_rna(o[nt][1] * i0));
        float2 v1 = make_float2(tf32_rna(o[nt][2] * i1), tf32_rna(o[nt][3] * i1));
        *(float2*)&out[(size_t)(b_ * SEQ + r0) * EMBD + h * 64 + d] = v0;
        *(float2*)&out[(size_t)(b_ * SEQ + r1) * EMBD + h * 64 + d] = v1;
    }
}

// ---------------------------------------------------------------------------
extern "C" void kernel_launch(void* const* d_in, const int* in_sizes, int n_in,
                              void* d_out, int out_size)
{
    const float* x      = (const float*)d_in[0];
    const float* qkv_w  = (const float*)d_in[1];
    const float* qkv_b  = (const float*)d_in[2];
    const float* proj_w = (const float*)d_in[3];
    const float* proj_b = (const float*)d_in[4];

    float* out  = (float*)d_out;
    float* outK = out  + (size_t)BATCH * SEQ * EMBD;
    float* outV = outK + (size_t)BATCH * SEQ * EMBD;

    float *qbuf, *abuf, *xrbuf, *wtq, *wtp;
    cudaGetSymbolAddress((void**)&qbuf,  g_q);
    cudaGetSymbolAddress((void**)&abuf,  g_attn);
    cudaGetSymbolAddress((void**)&xrbuf, g_xr);
    cudaGetSymbolAddress((void**)&wtq,   g_wt_qkv);
    cudaGetSymbolAddress((void**)&wtp,   g_wt_proj);

    const int gemm_smem  = 2 * 2 * 128 * GPAD * (int)sizeof(float);            // 73728
    const int flash_smem = (2 * 128 * FSTR + 4 * 64 * FSTR) * (int)sizeof(float); // 139264
    cudaFuncSetAttribute(gemm_tc,
                         cudaFuncAttributeMaxDynamicSharedMemorySize, gemm_smem);
    cudaFuncSetAttribute(flash_tc,
                         cudaFuncAttributeMaxDynamicSharedMemorySize, flash_smem);

    // 0) prep: RNA-round x; transpose+round weights to K-major
    round_tf32_kernel<<<(M_TOTAL * EMBD / 4 + 255) / 256, 256>>>(x, xrbuf, M_TOTAL * EMBD / 4);
    transpose_tf32_kernel<<<dim3(3 * EMBD / 32, EMBD / 32), dim3(32, 8)>>>(qkv_w, wtq, 3 * EMBD);
    transpose_tf32_kernel<<<dim3(EMBD / 32, EMBD / 32), dim3(32, 8)>>>(proj_w, wtp, EMBD);

    // 1) QKV GEMM -> Q scratch + K/V into d_out (all tf32-rounded)
    gemm_tc<<<dim3(3 * EMBD / 128, M_TOTAL / 128), 256, gemm_smem>>>(
        xrbuf, wtq, qkv_b, 0, qbuf, outK, outV);

    // 2) causal flash attention (tensor cores)
    flash_tc<<<dim3(SEQ / 128, BATCH * N_HEAD), 256, flash_smem>>>(
        qbuf, outK, outV, abuf);

    // 3) output projection
    gemm_tc<<<dim3(EMBD / 128, M_TOTAL / 128), 256, gemm_smem>>>(
        abuf, wtp, proj_b, 1, out, nullptr, nullptr);
}

// round 4
// speedup vs baseline: 3.3950x; 1.1549x over previous
#include <cuda_runtime.h>
#include <math.h>
#include <stdint.h>

#define N_HEAD   16
#define HEAD_DIM 64
#define EMBD     1024
#define BATCH    2
#define SEQ      2048
#define M_TOTAL  (BATCH*SEQ)   // 4096

// ---------------- scratch (device globals; no allocs allowed) ---------------
__device__ float g_q[(size_t)BATCH*N_HEAD*SEQ*HEAD_DIM];     // Q [B,H,S,D], tf32-rounded
__device__ float g_attn[(size_t)M_TOTAL*EMBD];               // attn out [B*S,E], rounded
__device__ float g_xr[(size_t)M_TOTAL*EMBD];                 // x rounded to tf32
__device__ float g_wt_qkv[(size_t)3*EMBD*EMBD];              // W_qkv^T [3072,1024], rounded
__device__ float g_wt_proj[(size_t)EMBD*EMBD];               // W_proj^T [1024,1024], rounded

// ---------------- helpers ---------------------------------------------------
__device__ __forceinline__ uint32_t smem_u32(const void* p) {
    uint32_t a;
    asm("{ .reg .u64 t; cvta.to.shared.u64 t, %1; cvt.u32.u64 %0, t; }" : "=r"(a) : "l"(p));
    return a;
}
__device__ __forceinline__ float tf32_rna(float x) {
    uint32_t u;
    asm("cvt.rna.tf32.f32 %0, %1;" : "=r"(u) : "f"(x));
    return __uint_as_float(u);
}
// D += A(16x8,row) * B(8x8,col), tf32 inputs in fp32 containers (pre-rounded RNA)
__device__ __forceinline__ void mma_tf32(float* c, const float* a, const float* b) {
    asm volatile("mma.sync.aligned.m16n8k8.row.col.f32.tf32.tf32.f32 "
        "{%0,%1,%2,%3}, {%4,%5,%6,%7}, {%8,%9}, {%0,%1,%2,%3};"
        : "+f"(c[0]), "+f"(c[1]), "+f"(c[2]), "+f"(c[3])
        : "r"(__float_as_uint(a[0])), "r"(__float_as_uint(a[1])),
          "r"(__float_as_uint(a[2])), "r"(__float_as_uint(a[3])),
          "r"(__float_as_uint(b[0])), "r"(__float_as_uint(b[1])));
}
__device__ __forceinline__ void cp16(void* dst_smem, const void* src) {
    uint32_t d = smem_u32(dst_smem);
    asm volatile("cp.async.cg.shared.global [%0], [%1], 16;" :: "r"(d), "l"(src) : "memory");
}
#define CP_COMMIT() asm volatile("cp.async.commit_group;" ::: "memory")
#define CP_WAIT(n)  asm volatile("cp.async.wait_group %0;" :: "n"(n) : "memory")

// ---------------- prep kernels ----------------------------------------------
__global__ __launch_bounds__(256)
void transpose_tf32_kernel(const float* __restrict__ W, float* __restrict__ WT, int N)
{
    __shared__ float t[32][33];
    int n0 = blockIdx.x * 32, k0 = blockIdx.y * 32;
    int tx = threadIdx.x, ty = threadIdx.y;
#pragma unroll
    for (int i = 0; i < 4; i++)
        t[ty + 8 * i][tx] = W[(size_t)(k0 + ty + 8 * i) * N + n0 + tx];
    __syncthreads();
#pragma unroll
    for (int i = 0; i < 4; i++)
        WT[(size_t)(n0 + ty + 8 * i) * EMBD + k0 + tx] = tf32_rna(t[tx][ty + 8 * i]);
}

__global__ __launch_bounds__(256)
void round_tf32_kernel(const float* __restrict__ x, float* __restrict__ y, int n4)
{
    int i = blockIdx.x * blockDim.x + threadIdx.x;
    if (i < n4) {
        float4 v = ((const float4*)x)[i];
        v.x = tf32_rna(v.x); v.y = tf32_rna(v.y);
        v.z = tf32_rna(v.z); v.w = tf32_rna(v.w);
        ((float4*)y)[i] = v;
    }
}

// ---------------- tf32 mma.sync GEMM (3-stage cp.async) ---------------------
// C[M,Ntot] = A[M,1024] @ Bt^T + bias.  A row-major K-contig; Bt [Ntot,1024] K-contig.
// Block 128x128, BK=32. 8 warps, each 32(M)x64(N). One barrier per K-tile.
#define GPAD 36
#define GKT  (EMBD/32)
#define GSTG 3

__global__ __launch_bounds__(256)
void gemm_tc(const float* __restrict__ A, const float* __restrict__ Bt,
             const float* __restrict__ bias, int mode,
             float* __restrict__ o0, float* __restrict__ o1, float* __restrict__ o2)
{
    extern __shared__ float smg[];
    float* SA = smg;                          // [GSTG][128*GPAD]
    float* SB = smg + GSTG * 128 * GPAD;      // [GSTG][128*GPAD]

    const int tid = threadIdx.x, wid = tid >> 5, lane = tid & 31;
    const int g = lane >> 2, t4 = lane & 3;
    const int wm = wid >> 1, wn = wid & 1;
    const int m0 = blockIdx.y * 128, n0 = blockIdx.x * 128;
    const float* Ab = A  + (size_t)m0 * EMBD;
    const float* Bb = Bt + (size_t)n0 * EMBD;

    float c[2][8][4];
#pragma unroll
    for (int mt = 0; mt < 2; mt++)
#pragma unroll
        for (int nt = 0; nt < 8; nt++)
#pragma unroll
            for (int e = 0; e < 4; e++) c[mt][nt][e] = 0.f;

    auto load_tile = [&](int t) {
        float* as = SA + (t % GSTG) * 128 * GPAD;
        float* bs = SB + (t % GSTG) * 128 * GPAD;
        int kt = t * 32;
#pragma unroll
        for (int i = 0; i < 4; i++) {
            int idx = tid + i * 256;
            int r = idx >> 3, ch = idx & 7;
            cp16(as + r * GPAD + ch * 4, Ab + (size_t)r * EMBD + kt + ch * 4);
        }
#pragma unroll
        for (int i = 0; i < 4; i++) {
            int idx = tid + i * 256;
            int r = idx >> 3, ch = idx & 7;
            cp16(bs + r * GPAD + ch * 4, Bb + (size_t)r * EMBD + kt + ch * 4);
        }
    };

    load_tile(0); CP_COMMIT();
    load_tile(1); CP_COMMIT();

    for (int t = 0; t < GKT; t++) {
        CP_WAIT(1);            // group t complete (t+1 may be pending)
        __syncthreads();       // all warps past reads of buf (t-1)%3; data t visible
        if (t + 2 < GKT) { load_tile(t + 2); CP_COMMIT(); }
        else             { CP_COMMIT(); }    // empty group keeps accounting
        const float* as = SA + (t % GSTG) * 128 * GPAD;
        const float* bs = SB + (t % GSTG) * 128 * GPAD;
#pragma unroll
        for (int k8 = 0; k8 < 4; k8++) {
            int k0 = k8 * 8;
            float a[2][4], b[8][2];
#pragma unroll
            for (int mt = 0; mt < 2; mt++) {
                int rb = wm * 32 + mt * 16;
                a[mt][0] = as[(rb + g)     * GPAD + k0 + t4];
                a[mt][1] = as[(rb + 8 + g) * GPAD + k0 + t4];
                a[mt][2] = as[(rb + g)     * GPAD + k0 + 4 + t4];
                a[mt][3] = as[(rb + 8 + g) * GPAD + k0 + 4 + t4];
            }
#pragma unroll
            for (int nt = 0; nt < 8; nt++) {
                int cb = wn * 64 + nt * 8;
                b[nt][0] = bs[(cb + g) * GPAD + k0 + t4];
                b[nt][1] = bs[(cb + g) * GPAD + k0 + 4 + t4];
            }
#pragma unroll
            for (int mt = 0; mt < 2; mt++)
#pragma unroll
                for (int nt = 0; nt < 8; nt++)
                    mma_tf32(c[mt][nt], a[mt], b[nt]);
        }
    }

    // epilogue
#pragma unroll
    for (int mt = 0; mt < 2; mt++) {
#pragma unroll
        for (int nt = 0; nt < 8; nt++) {
            int row0 = m0 + wm * 32 + mt * 16 + g;
            int row1 = row0 + 8;
            int col  = n0 + wn * 64 + nt * 8 + 2 * t4;
            float b0 = bias[col], b1 = bias[col + 1];
            float2 v0 = make_float2(c[mt][nt][0] + b0, c[mt][nt][1] + b1);
            float2 v1 = make_float2(c[mt][nt][2] + b0, c[mt][nt][3] + b1);
            if (mode == 0) {
                // Q/K/V are future MMA operands: RNA-round now
                v0.x = tf32_rna(v0.x); v0.y = tf32_rna(v0.y);
                v1.x = tf32_rna(v1.x); v1.y = tf32_rna(v1.y);
                int sec = col >> 10, nn = col & 1023;
                int h = nn >> 6, d = nn & 63;
                float* dst = (sec == 0) ? o0 : (sec == 1) ? o1 : o2;
                int b_0 = row0 >> 11, s_0 = row0 & 2047;
                int b_1 = row1 >> 11, s_1 = row1 & 2047;
                *(float2*)&dst[(((size_t)(b_0 * N_HEAD + h) * SEQ + s_0) << 6) + d] = v0;
                *(float2*)&dst[(((size_t)(b_1 * N_HEAD + h) * SEQ + s_1) << 6) + d] = v1;
            } else {
                *(float2*)&o0[(size_t)row0 * EMBD + col] = v0;
                *(float2*)&o0[(size_t)row1 * EMBD + col] = v1;
            }
        }
    }
}

// ---------------- flash attention, tf32 mma, P kept in registers ------------
// Block: 128 queries x one (b,h); 8 warps, warp = 16 rows x full 64 cols.
// PV consumes the S C-fragment directly as an A-fragment via the column
// permutation trick: a = {c0,c2,c1,c3} paired with V rows (8k8+2t4, 8k8+2t4+1).
#define FSTR 68

__global__ __launch_bounds__(256)
void flash_tc(const float* __restrict__ q, const float* __restrict__ k,
              const float* __restrict__ v, float* __restrict__ out)
{
    extern __shared__ float smf[];
    float* Qs = smf;                    // [128][FSTR]
    float* Ks = smf + 128 * FSTR;       // [2][64][FSTR]
    float* Vs = Ks + 2 * 64 * FSTR;     // [2][64][FSTR]

    const int tid = threadIdx.x, wid = tid >> 5, lane = tid & 31;
    const int g = lane >> 2, t4 = lane & 3;
    const int qb = gridDim.x - 1 - blockIdx.x;   // big causal blocks first
    const int bh = blockIdx.y;
    const int q0 = qb * 128;
    const size_t base = (size_t)bh * SEQ * HEAD_DIM;
    const int qw = q0 + wid * 16;       // warp's first query row
    const int jtmax = 2 * qb + 1;

    auto load_kv = [&](int jt) {
        float* kd = Ks + (jt & 1) * 64 * FSTR;
        float* vd = Vs + (jt & 1) * 64 * FSTR;
        const float* kg = k + base + (size_t)jt * 64 * 64;
        const float* vg = v + base + (size_t)jt * 64 * 64;
#pragma unroll
        for (int i = 0; i < 4; i++) {
            int idx = tid + i * 256;
            int r = idx >> 4, ch = idx & 15;
            cp16(kd + r * FSTR + ch * 4, kg + (size_t)r * 64 + ch * 4);
            cp16(vd + r * FSTR + ch * 4, vg + (size_t)r * 64 + ch * 4);
        }
    };

    // Q tile (already tf32-rounded by QKV epilogue) + first KV tile
#pragma unroll
    for (int i = 0; i < 8; i++) {
        int idx = tid + i * 256;
        int r = idx >> 4, ch = idx & 15;
        cp16(Qs + r * FSTR + ch * 4, q + base + (size_t)(q0 + r) * 64 + ch * 4);
    }
    load_kv(0);
    CP_COMMIT();

    float mr[2] = {-1e30f, -1e30f}, lr[2] = {0.f, 0.f};
    float o[8][4];
#pragma unroll
    for (int nt = 0; nt < 8; nt++)
#pragma unroll
        for (int e = 0; e < 4; e++) o[nt][e] = 0.f;

    for (int jt = 0; jt <= jtmax; jt++) {
        if (jt < jtmax) { load_kv(jt + 1); CP_COMMIT(); CP_WAIT(1); }
        else            { CP_WAIT(0); }
        __syncthreads();
        const float* Kb = Ks + (jt & 1) * 64 * FSTR;
        const float* Vb = Vs + (jt & 1) * 64 * FSTR;

        if (jt * 64 <= qw + 15) {       // warp has at least one unmasked element
            // ---- S = Q K^T (16x64) ----
            float s[8][4];
#pragma unroll
            for (int nt = 0; nt < 8; nt++)
#pragma unroll
                for (int e = 0; e < 4; e++) s[nt][e] = 0.f;
#pragma unroll
            for (int k8 = 0; k8 < 8; k8++) {
                int k0 = k8 * 8;
                float aq[4];
                aq[0] = Qs[(wid * 16 + g)     * FSTR + k0 + t4];
                aq[1] = Qs[(wid * 16 + 8 + g) * FSTR + k0 + t4];
                aq[2] = Qs[(wid * 16 + g)     * FSTR + k0 + 4 + t4];
                aq[3] = Qs[(wid * 16 + 8 + g) * FSTR + k0 + 4 + t4];
#pragma unroll
                for (int nt = 0; nt < 8; nt++) {
                    float bk[2];
                    bk[0] = Kb[(nt * 8 + g) * FSTR + k0 + t4];
                    bk[1] = Kb[(nt * 8 + g) * FSTR + k0 + 4 + t4];
                    mma_tf32(s[nt], aq, bk);
                }
            }
            // ---- scale + causal mask ----
            bool diag = (jt * 64 + 63 > qw);
#pragma unroll
            for (int nt = 0; nt < 8; nt++) {
                int colb = jt * 64 + nt * 8 + 2 * t4;
#pragma unroll
                for (int e = 0; e < 4; e++) {
                    int row = qw + g + (e >> 1) * 8;
                    int col = colb + (e & 1);
                    s[nt][e] *= 0.125f;
                    if (diag && col > row) s[nt][e] = -1e30f;
                }
            }
            // ---- online softmax (rows live in a quad: shfl over lanes 1,2) ----
            float mx0 = -1e30f, mx1 = -1e30f;
#pragma unroll
            for (int nt = 0; nt < 8; nt++) {
                mx0 = fmaxf(mx0, fmaxf(s[nt][0], s[nt][1]));
                mx1 = fmaxf(mx1, fmaxf(s[nt][2], s[nt][3]));
            }
            mx0 = fmaxf(mx0, __shfl_xor_sync(0xffffffffu, mx0, 1));
            mx0 = fmaxf(mx0, __shfl_xor_sync(0xffffffffu, mx0, 2));
            mx1 = fmaxf(mx1, __shfl_xor_sync(0xffffffffu, mx1, 1));
            mx1 = fmaxf(mx1, __shfl_xor_sync(0xffffffffu, mx1, 2));
            float mn0 = fmaxf(mr[0], mx0), mn1 = fmaxf(mr[1], mx1);
            float al0 = __expf(mr[0] - mn0), al1 = __expf(mr[1] - mn1);
            mr[0] = mn0; mr[1] = mn1;
            float sum0 = 0.f, sum1 = 0.f;
#pragma unroll
            for (int nt = 0; nt < 8; nt++) {
                s[nt][0] = __expf(s[nt][0] - mn0); sum0 += s[nt][0];
                s[nt][1] = __expf(s[nt][1] - mn0); sum0 += s[nt][1];
                s[nt][2] = __expf(s[nt][2] - mn1); sum1 += s[nt][2];
                s[nt][3] = __expf(s[nt][3] - mn1); sum1 += s[nt][3];
            }
            sum0 += __shfl_xor_sync(0xffffffffu, sum0, 1);
            sum0 += __shfl_xor_sync(0xffffffffu, sum0, 2);
            sum1 += __shfl_xor_sync(0xffffffffu, sum1, 1);
            sum1 += __shfl_xor_sync(0xffffffffu, sum1, 2);
            lr[0] = lr[0] * al0 + sum0;
            lr[1] = lr[1] * al1 + sum1;
#pragma unroll
            for (int nt = 0; nt < 8; nt++) {
                o[nt][0] *= al0; o[nt][1] *= al0;
                o[nt][2] *= al1; o[nt][3] *= al1;
            }
            // ---- O += P V : P straight from registers (C-frag -> A-frag) ----
            // a = {c0,c2,c1,c3}; b-frag rows of V: (8k8+2t4, 8k8+2t4+1).
            // Bank check: (8k8+2t4)*FSTR + nt*8+g mod 32 = 8t4+g+const -> bijective.
#pragma unroll
            for (int k8 = 0; k8 < 8; k8++) {
                float ap[4];
                ap[0] = tf32_rna(s[k8][0]);
                ap[1] = tf32_rna(s[k8][2]);
                ap[2] = tf32_rna(s[k8][1]);
                ap[3] = tf32_rna(s[k8][3]);
                int r0 = k8 * 8 + 2 * t4;
#pragma unroll
                for (int nt = 0; nt < 8; nt++) {
                    float bv[2];
                    bv[0] = Vb[(r0)     * FSTR + nt * 8 + g];
                    bv[1] = Vb[(r0 + 1) * FSTR + nt * 8 + g];
                    mma_tf32(o[nt], ap, bv);
                }
            }
        }
        __syncthreads();
    }

    // ---- normalize + store (RNA-rounded: A operand of proj GEMM) ----
    int b_ = bh >> 4, h = bh & 15;
    float i0 = 1.f / lr[0], i1 = 1.f / lr[1];
#pragma unroll
    for (int nt = 0; nt < 8; nt++) {
        int d = nt * 8 + 2 * t4;
        int r0 = qw + g, r1 = qw + 8 + g;
        float2 v0 = make_float2(tf32_rna(o[nt][0] * i0), tf32_rna(o[nt][1] * i0));
        float2 v1 = make_float2(tf32_rna(o[nt][2] * i1), tf32_rna(o[nt][3] * i1));
        *(float2*)&out[(size_t)(b_ * SEQ + r0) * EMBD + h * 64 + d] = v0;
        *(float2*)&out[(size_t)(b_ * SEQ + r1) * EMBD + h * 64 + d] = v1;
    }
}

// ---------------------------------------------------------------------------
extern "C" void kernel_launch(void* const* d_in, const int* in_sizes, int n_in,
                              void* d_out, int out_size)
{
    const float* x      = (const float*)d_in[0];
    const float* qkv_w  = (const float*)d_in[1];
    const float* qkv_b  = (const float*)d_in[2];
    const float* proj_w = (const float*)d_in[3];
    const float* proj_b = (const float*)d_in[4];

    float* out  = (float*)d_out;
    float* outK = out  + (size_t)BATCH * SEQ * EMBD;
    float* outV = outK + (size_t)BATCH * SEQ * EMBD;

    float *qbuf, *abuf, *xrbuf, *wtq, *wtp;
    cudaGetSymbolAddress((void**)&qbuf,  g_q);
    cudaGetSymbolAddress((void**)&abuf,  g_attn);
    cudaGetSymbolAddress((void**)&xrbuf, g_xr);
    cudaGetSymbolAddress((void**)&wtq,   g_wt_qkv);
    cudaGetSymbolAddress((void**)&wtp,   g_wt_proj);

    const int gemm_smem  = GSTG * 2 * 128 * GPAD * (int)sizeof(float);            // 110592
    const int flash_smem = (128 * FSTR + 4 * 64 * FSTR) * (int)sizeof(float);     // 104448
    cudaFuncSetAttribute(gemm_tc,
                         cudaFuncAttributeMaxDynamicSharedMemorySize, gemm_smem);
    cudaFuncSetAttribute(flash_tc,
                         cudaFuncAttributeMaxDynamicSharedMemorySize, flash_smem);

    // 0) prep: RNA-round x; transpose+round weights to K-major
    round_tf32_kernel<<<(M_TOTAL * EMBD / 4 + 255) / 256, 256>>>(x, xrbuf, M_TOTAL * EMBD / 4);
    transpose_tf32_kernel<<<dim3(3 * EMBD / 32, EMBD / 32), dim3(32, 8)>>>(qkv_w, wtq, 3 * EMBD);
    transpose_tf32_kernel<<<dim3(EMBD / 32, EMBD / 32), dim3(32, 8)>>>(proj_w, wtp, EMBD);

    // 1) QKV GEMM -> Q scratch + K/V into d_out (all tf32-rounded)
    gemm_tc<<<dim3(3 * EMBD / 128, M_TOTAL / 128), 256, gemm_smem>>>(
        xrbuf, wtq, qkv_b, 0, qbuf, outK, outV);

    // 2) causal flash attention (tensor cores, register-resident P)
    flash_tc<<<dim3(SEQ / 128, BATCH * N_HEAD), 256, flash_smem>>>(
        qbuf, outK, outV, abuf);

    // 3) output projection
    gemm_tc<<<dim3(EMBD / 128, M_TOTAL / 128), 256, gemm_smem>>>(
        abuf, wtp, proj_b, 1, out, nullptr, nullptr);
}

// round 5
// speedup vs baseline: 3.4254x; 1.0089x over previous
#include <cuda_runtime.h>
#include <math.h>
#include <stdint.h>

#define N_HEAD   16
#define HEAD_DIM 64
#define EMBD     1024
#define BATCH    2
#define SEQ      2048
#define M_TOTAL  (BATCH*SEQ)   // 4096

// K-dim permutation (within 8-groups): position p holds original k=(p&1)*4+(p>>1).
// Both MMA operands permuted identically -> dot products unchanged, and each
// thread's tf32 fragment pair {k=t4, k=t4+4} sits at {2*t4, 2*t4+1} -> LDS.64.

// ---------------- scratch (device globals; no allocs allowed) ---------------
__device__ float g_q[(size_t)BATCH*N_HEAD*SEQ*HEAD_DIM];     // Q [B,H,S,D], d-permuted
__device__ float g_kp[(size_t)BATCH*N_HEAD*SEQ*HEAD_DIM];    // K copy, d-permuted
__device__ float g_attn[(size_t)M_TOTAL*EMBD];               // attn out, k-permuted
__device__ float g_xr[(size_t)M_TOTAL*EMBD];                 // x tf32-rounded, k-permuted
__device__ float g_wt_qkv[(size_t)3*EMBD*EMBD];              // W_qkv^T, k-permuted
__device__ float g_wt_proj[(size_t)EMBD*EMBD];               // W_proj^T, k-permuted

// ---------------- helpers ---------------------------------------------------
__device__ __forceinline__ uint32_t smem_u32(const void* p) {
    uint32_t a;
    asm("{ .reg .u64 t; cvta.to.shared.u64 t, %1; cvt.u32.u64 %0, t; }" : "=r"(a) : "l"(p));
    return a;
}
__device__ __forceinline__ float tf32_rna(float x) {
    uint32_t u;
    asm("cvt.rna.tf32.f32 %0, %1;" : "=r"(u) : "f"(x));
    return __uint_as_float(u);
}
__device__ __forceinline__ void mma_tf32(float* c, const float* a, const float* b) {
    asm volatile("mma.sync.aligned.m16n8k8.row.col.f32.tf32.tf32.f32 "
        "{%0,%1,%2,%3}, {%4,%5,%6,%7}, {%8,%9}, {%0,%1,%2,%3};"
        : "+f"(c[0]), "+f"(c[1]), "+f"(c[2]), "+f"(c[3])
        : "r"(__float_as_uint(a[0])), "r"(__float_as_uint(a[1])),
          "r"(__float_as_uint(a[2])), "r"(__float_as_uint(a[3])),
          "r"(__float_as_uint(b[0])), "r"(__float_as_uint(b[1])));
}
__device__ __forceinline__ void cp16(void* dst_smem, const void* src) {
    uint32_t d = smem_u32(dst_smem);
    asm volatile("cp.async.cg.shared.global [%0], [%1], 16;" :: "r"(d), "l"(src) : "memory");
}
#define CP_COMMIT() asm volatile("cp.async.commit_group;" ::: "memory")
#define CP_WAIT(n)  asm volatile("cp.async.wait_group %0;" :: "n"(n) : "memory")

// ---------------- prep kernels ----------------------------------------------
// Transpose W [1024, N] -> WT [N, 1024], tf32-rounded, k-permuted within 8-groups.
__global__ __launch_bounds__(256)
void transpose_tf32_kernel(const float* __restrict__ W, float* __restrict__ WT, int N)
{
    __shared__ float t[32][33];
    int n0 = blockIdx.x * 32, k0 = blockIdx.y * 32;
    int tx = threadIdx.x, ty = threadIdx.y;
#pragma unroll
    for (int i = 0; i < 4; i++)
        t[ty + 8 * i][tx] = W[(size_t)(k0 + ty + 8 * i) * N + n0 + tx];
    __syncthreads();
#pragma unroll
    for (int i = 0; i < 4; i++) {
        int kk = tx;                                  // 0..31 within this 32-block
        int kp = (kk & ~7) | (((kk & 3) << 1) | (kk >> 2 & 1));  // p(k)
        WT[(size_t)(n0 + ty + 8 * i) * EMBD + k0 + kp] = tf32_rna(t[tx][ty + 8 * i]);
    }
}

// Round x to tf32 and k-permute: out 8-group = {x0,x4,x1,x5,x2,x6,x3,x7}
__global__ __launch_bounds__(256)
void round_tf32_kernel(const float* __restrict__ x, float* __restrict__ y, int n8)
{
    int i = blockIdx.x * blockDim.x + threadIdx.x;
    if (i < n8) {
        float4 lo = ((const float4*)x)[2 * i];
        float4 hi = ((const float4*)x)[2 * i + 1];
        float4 olo, ohi;
        olo.x = tf32_rna(lo.x); olo.y = tf32_rna(hi.x);
        olo.z = tf32_rna(lo.y); olo.w = tf32_rna(hi.y);
        ohi.x = tf32_rna(lo.z); ohi.y = tf32_rna(hi.z);
        ohi.z = tf32_rna(lo.w); ohi.w = tf32_rna(hi.w);
        ((float4*)y)[2 * i]     = olo;
        ((float4*)y)[2 * i + 1] = ohi;
    }
}

// ---------------- tf32 mma.sync GEMM (k-permuted operands, LDS.64 frags) -----
#define GPAD 40      // pair-stride 20 == 4 (mod 16) -> conflict-free LDS.64
#define GKT  (EMBD/32)

__global__ __launch_bounds__(256)
void gemm_tc(const float* __restrict__ A, const float* __restrict__ Bt,
             const float* __restrict__ bias, int mode,
             float* __restrict__ o0, float* __restrict__ o1, float* __restrict__ o2,
             float* __restrict__ o3)
{
    extern __shared__ float smg[];
    float* SA = smg;                       // [2][128*GPAD]
    float* SB = smg + 2 * 128 * GPAD;      // [2][128*GPAD]

    const int tid = threadIdx.x, wid = tid >> 5, lane = tid & 31;
    const int g = lane >> 2, t4 = lane & 3;
    const int wm = wid >> 1, wn = wid & 1;
    const int m0 = blockIdx.y * 128, n0 = blockIdx.x * 128;
    const float* Ab = A  + (size_t)m0 * EMBD;
    const float* Bb = Bt + (size_t)n0 * EMBD;

    float c[2][8][4];
#pragma unroll
    for (int mt = 0; mt < 2; mt++)
#pragma unroll
        for (int nt = 0; nt < 8; nt++)
#pragma unroll
            for (int e = 0; e < 4; e++) c[mt][nt][e] = 0.f;

    auto load_tile = [&](int t) {
        float* as = SA + (t & 1) * 128 * GPAD;
        float* bs = SB + (t & 1) * 128 * GPAD;
        int kt = t * 32;
#pragma unroll
        for (int i = 0; i < 4; i++) {
            int idx = tid + i * 256;
            int r = idx >> 3, ch = idx & 7;
            cp16(as + r * GPAD + ch * 4, Ab + (size_t)r * EMBD + kt + ch * 4);
        }
#pragma unroll
        for (int i = 0; i < 4; i++) {
            int idx = tid + i * 256;
            int r = idx >> 3, ch = idx & 7;
            cp16(bs + r * GPAD + ch * 4, Bb + (size_t)r * EMBD + kt + ch * 4);
        }
    };

    load_tile(0); CP_COMMIT();

    for (int t = 0; t < GKT; t++) {
        CP_WAIT(0);            // tile t resident
        __syncthreads();       // all warps done reading buf (t+1)&1 (iter t-1)
        if (t + 1 < GKT) { load_tile(t + 1); CP_COMMIT(); }
        const float* as = SA + (t & 1) * 128 * GPAD;
        const float* bs = SB + (t & 1) * 128 * GPAD;
#pragma unroll
        for (int k8 = 0; k8 < 4; k8++) {
            int k0 = k8 * 8 + 2 * t4;
            float a[2][4], b[8][2];
#pragma unroll
            for (int mt = 0; mt < 2; mt++) {
                int rb = wm * 32 + mt * 16;
                float2 p0 = *(const float2*)&as[(rb + g)     * GPAD + k0];
                float2 p1 = *(const float2*)&as[(rb + 8 + g) * GPAD + k0];
                a[mt][0] = p0.x; a[mt][1] = p1.x; a[mt][2] = p0.y; a[mt][3] = p1.y;
            }
#pragma unroll
            for (int nt = 0; nt < 8; nt++) {
                int cb = wn * 64 + nt * 8;
                float2 pb = *(const float2*)&bs[(cb + g) * GPAD + k0];
                b[nt][0] = pb.x; b[nt][1] = pb.y;
            }
#pragma unroll
            for (int mt = 0; mt < 2; mt++)
#pragma unroll
                for (int nt = 0; nt < 8; nt++)
                    mma_tf32(c[mt][nt], a[mt], b[nt]);
        }
    }

    // epilogue. P0 = permuted position of within-group col 2*t4 (pair partner at +2)
    const int P0 = ((t4 & 1) << 2) | (t4 >> 1);
#pragma unroll
    for (int mt = 0; mt < 2; mt++) {
#pragma unroll
        for (int nt = 0; nt < 8; nt++) {
            int row0 = m0 + wm * 32 + mt * 16 + g;
            int row1 = row0 + 8;
            int col  = n0 + wn * 64 + nt * 8 + 2 * t4;
            float b0 = bias[col], b1 = bias[col + 1];
            float2 v0 = make_float2(c[mt][nt][0] + b0, c[mt][nt][1] + b1);
            float2 v1 = make_float2(c[mt][nt][2] + b0, c[mt][nt][3] + b1);
            if (mode == 0) {
                v0.x = tf32_rna(v0.x); v0.y = tf32_rna(v0.y);
                v1.x = tf32_rna(v1.x); v1.y = tf32_rna(v1.y);
                int sec = col >> 10, nn = col & 1023;
                int h = nn >> 6, d = nn & 63;
                int b_0 = row0 >> 11, s_0 = row0 & 2047;
                int b_1 = row1 >> 11, s_1 = row1 & 2047;
                size_t i0 = (((size_t)(b_0 * N_HEAD + h) * SEQ + s_0) << 6);
                size_t i1 = (((size_t)(b_1 * N_HEAD + h) * SEQ + s_1) << 6);
                int dgrp = d & ~7;
                if (sec == 0) {            // Q: permuted only (scratch)
                    o0[i0 + dgrp + P0]     = v0.x; o0[i0 + dgrp + P0 + 2] = v0.y;
                    o0[i1 + dgrp + P0]     = v1.x; o0[i1 + dgrp + P0 + 2] = v1.y;
                } else if (sec == 1) {     // K: canonical output + permuted copy
                    *(float2*)&o1[i0 + d] = v0;
                    *(float2*)&o1[i1 + d] = v1;
                    o3[i0 + dgrp + P0]     = v0.x; o3[i0 + dgrp + P0 + 2] = v0.y;
                    o3[i1 + dgrp + P0]     = v1.x; o3[i1 + dgrp + P0 + 2] = v1.y;
                } else {                   // V: canonical output
                    *(float2*)&o2[i0 + d] = v0;
                    *(float2*)&o2[i1 + d] = v1;
                }
            } else {
                *(float2*)&o0[(size_t)row0 * EMBD + col] = v0;
                *(float2*)&o0[(size_t)row1 * EMBD + col] = v1;
            }
        }
    }
}

// ---------------- flash attention (tf32 mma, LDS.64 QK frags) ---------------
#define FQ 72   // Q/K stride: pair-stride 36 == 4 (mod 16) -> LDS.64 conflict-free
#define FV 68   // V stride: scalar column reads conflict-free

__global__ __launch_bounds__(256)
void flash_tc(const float* __restrict__ q, const float* __restrict__ k,
              const float* __restrict__ v, float* __restrict__ out)
{
    extern __shared__ float smf[];
    float* Qs = smf;                    // [128][FQ]
    float* Ks = smf + 128 * FQ;         // [2][64][FQ]
    float* Vs = Ks + 2 * 64 * FQ;       // [2][64][FV]

    const int tid = threadIdx.x, wid = tid >> 5, lane = tid & 31;
    const int g = lane >> 2, t4 = lane & 3;
    const int qb = gridDim.x - 1 - blockIdx.x;   // big causal blocks first
    const int bh = blockIdx.y;
    const int q0 = qb * 128;
    const size_t base = (size_t)bh * SEQ * HEAD_DIM;
    const int qw = q0 + wid * 16;
    const int jtmax = 2 * qb + 1;

    auto load_kv = [&](int jt) {
        float* kd = Ks + (jt & 1) * 64 * FQ;
        float* vd = Vs + (jt & 1) * 64 * FV;
        const float* kg = k + base + (size_t)jt * 64 * 64;
        const float* vg = v + base + (size_t)jt * 64 * 64;
#pragma unroll
        for (int i = 0; i < 4; i++) {
            int idx = tid + i * 256;
            int r = idx >> 4, ch = idx & 15;
            cp16(kd + r * FQ + ch * 4, kg + (size_t)r * 64 + ch * 4);
            cp16(vd + r * FV + ch * 4, vg + (size_t)r * 64 + ch * 4);
        }
    };

#pragma unroll
    for (int i = 0; i < 8; i++) {
        int idx = tid + i * 256;
        int r = idx >> 4, ch = idx & 15;
        cp16(Qs + r * FQ + ch * 4, q + base + (size_t)(q0 + r) * 64 + ch * 4);
    }
    load_kv(0);
    CP_COMMIT();

    float mr[2] = {-1e30f, -1e30f}, lr[2] = {0.f, 0.f};
    float o[8][4];
#pragma unroll
    for (int nt = 0; nt < 8; nt++)
#pragma unroll
        for (int e = 0; e < 4; e++) o[nt][e] = 0.f;

    for (int jt = 0; jt <= jtmax; jt++) {
        if (jt < jtmax) { load_kv(jt + 1); CP_COMMIT(); CP_WAIT(1); }
        else            { CP_WAIT(0); }
        __syncthreads();
        const float* Kb = Ks + (jt & 1) * 64 * FQ;
        const float* Vb = Vs + (jt & 1) * 64 * FV;

        if (jt * 64 <= qw + 15) {
            // ---- S = Q K^T (d-permuted on both sides -> LDS.64 frags) ----
            float s[8][4];
#pragma unroll
            for (int nt = 0; nt < 8; nt++)
#pragma unroll
                for (int e = 0; e < 4; e++) s[nt][e] = 0.f;
#pragma unroll
            for (int k8 = 0; k8 < 8; k8++) {
                int k0 = k8 * 8 + 2 * t4;
                float aq[4];
                float2 p0 = *(const float2*)&Qs[(wid * 16 + g)     * FQ + k0];
                float2 p1 = *(const float2*)&Qs[(wid * 16 + 8 + g) * FQ + k0];
                aq[0] = p0.x; aq[1] = p1.x; aq[2] = p0.y; aq[3] = p1.y;
#pragma unroll
                for (int nt = 0; nt < 8; nt++) {
                    float2 pb = *(const float2*)&Kb[(nt * 8 + g) * FQ + k0];
                    float bk[2] = {pb.x, pb.y};
                    mma_tf32(s[nt], aq, bk);
                }
            }
            // ---- scale + causal mask ----
            bool diag = (jt * 64 + 63 > qw);
#pragma unroll
            for (int nt = 0; nt < 8; nt++) {
                int colb = jt * 64 + nt * 8 + 2 * t4;
#pragma unroll
                for (int e = 0; e < 4; e++) {
                    int row = qw + g + (e >> 1) * 8;
                    int col = colb + (e & 1);
                    s[nt][e] *= 0.125f;
                    if (diag && col > row) s[nt][e] = -1e30f;
                }
            }
            // ---- online softmax ----
            float mx0 = -1e30f, mx1 = -1e30f;
#pragma unroll
            for (int nt = 0; nt < 8; nt++) {
                mx0 = fmaxf(mx0, fmaxf(s[nt][0], s[nt][1]));
                mx1 = fmaxf(mx1, fmaxf(s[nt][2], s[nt][3]));
            }
            mx0 = fmaxf(mx0, __shfl_xor_sync(0xffffffffu, mx0, 1));
            mx0 = fmaxf(mx0, __shfl_xor_sync(0xffffffffu, mx0, 2));
            mx1 = fmaxf(mx1, __shfl_xor_sync(0xffffffffu, mx1, 1));
            mx1 = fmaxf(mx1, __shfl_xor_sync(0xffffffffu, mx1, 2));
            float mn0 = fmaxf(mr[0], mx0), mn1 = fmaxf(mr[1], mx1);
            float al0 = __expf(mr[0] - mn0), al1 = __expf(mr[1] - mn1);
            mr[0] = mn0; mr[1] = mn1;
            float sum0 = 0.f, sum1 = 0.f;
#pragma unroll
            for (int nt = 0; nt < 8; nt++) {
                s[nt][0] = __expf(s[nt][0] - mn0); sum0 += s[nt][0];
                s[nt][1] = __expf(s[nt][1] - mn0); sum0 += s[nt][1];
                s[nt][2] = __expf(s[nt][2] - mn1); sum1 += s[nt][2];
                s[nt][3] = __expf(s[nt][3] - mn1); sum1 += s[nt][3];
            }
            sum0 += __shfl_xor_sync(0xffffffffu, sum0, 1);
            sum0 += __shfl_xor_sync(0xffffffffu, sum0, 2);
            sum1 += __shfl_xor_sync(0xffffffffu, sum1, 1);
            sum1 += __shfl_xor_sync(0xffffffffu, sum1, 2);
            lr[0] = lr[0] * al0 + sum0;
            lr[1] = lr[1] * al1 + sum1;
#pragma unroll
            for (int nt = 0; nt < 8; nt++) {
                o[nt][0] *= al0; o[nt][1] *= al0;
                o[nt][2] *= al1; o[nt][3] *= al1;
            }
            // ---- O += P V (P from registers; k-dim = key pos, unpermuted) ----
#pragma unroll
            for (int k8 = 0; k8 < 8; k8++) {
                float ap[4];
                ap[0] = tf32_rna(s[k8][0]);
                ap[1] = tf32_rna(s[k8][2]);
                ap[2] = tf32_rna(s[k8][1]);
                ap[3] = tf32_rna(s[k8][3]);
                int r0 = k8 * 8 + 2 * t4;
#pragma unroll
                for (int nt = 0; nt < 8; nt++) {
                    float bv[2];
                    bv[0] = Vb[(r0)     * FV + nt * 8 + g];
                    bv[1] = Vb[(r0 + 1) * FV + nt * 8 + g];
                    mma_tf32(o[nt], ap, bv);
                }
            }
        }
        __syncthreads();
    }

    // ---- normalize + store k-permuted (A operand of proj GEMM) ----
    int b_ = bh >> 4, h = bh & 15;
    float i0 = 1.f / lr[0], i1 = 1.f / lr[1];
    const int P0 = ((t4 & 1) << 2) | (t4 >> 1);
#pragma unroll
    for (int nt = 0; nt < 8; nt++) {
        int dbase = h * 64 + nt * 8;
        int r0 = qw + g, r1 = qw + 8 + g;
        float* o0p = &out[(size_t)(b_ * SEQ + r0) * EMBD + dbase];
        float* o1p = &out[(size_t)(b_ * SEQ + r1) * EMBD + dbase];
        o0p[P0]     = tf32_rna(o[nt][0] * i0);
        o0p[P0 + 2] = tf32_rna(o[nt][1] * i0);
        o1p[P0]     = tf32_rna(o[nt][2] * i1);
        o1p[P0 + 2] = tf32_rna(o[nt][3] * i1);
    }
}

// ---------------------------------------------------------------------------
extern "C" void kernel_launch(void* const* d_in, const int* in_sizes, int n_in,
                              void* d_out, int out_size)
{
    const float* x      = (const float*)d_in[0];
    const float* qkv_w  = (const float*)d_in[1];
    const float* qkv_b  = (const float*)d_in[2];
    const float* proj_w = (const float*)d_in[3];
    const float* proj_b = (const float*)d_in[4];

    float* out  = (float*)d_out;
    float* outK = out  + (size_t)BATCH * SEQ * EMBD;
    float* outV = outK + (size_t)BATCH * SEQ * EMBD;

    float *qbuf, *kpbuf, *abuf, *xrbuf, *wtq, *wtp;
    cudaGetSymbolAddress((void**)&qbuf,  g_q);
    cudaGetSymbolAddress((void**)&kpbuf, g_kp);
    cudaGetSymbolAddress((void**)&abuf,  g_attn);
    cudaGetSymbolAddress((void**)&xrbuf, g_xr);
    cudaGetSymbolAddress((void**)&wtq,   g_wt_qkv);
    cudaGetSymbolAddress((void**)&wtp,   g_wt_proj);

    const int gemm_smem  = 2 * 2 * 128 * GPAD * (int)sizeof(float);               // 81920
    const int flash_smem = (128 * FQ + 2 * 64 * FQ + 2 * 64 * FV) * (int)sizeof(float); // 108544
    cudaFuncSetAttribute(gemm_tc,
                         cudaFuncAttributeMaxDynamicSharedMemorySize, gemm_smem);
    cudaFuncSetAttribute(flash_tc,
                         cudaFuncAttributeMaxDynamicSharedMemorySize, flash_smem);

    // 0) prep: RNA-round + k-permute x; transpose + round + k-permute weights
    round_tf32_kernel<<<(M_TOTAL * EMBD / 8 + 255) / 256, 256>>>(x, xrbuf, M_TOTAL * EMBD / 8);
    transpose_tf32_kernel<<<dim3(3 * EMBD / 32, EMBD / 32), dim3(32, 8)>>>(qkv_w, wtq, 3 * EMBD);
    transpose_tf32_kernel<<<dim3(EMBD / 32, EMBD / 32), dim3(32, 8)>>>(proj_w, wtp, EMBD);

    // 1) QKV GEMM -> Qp scratch, K canonical + Kp scratch, V canonical
    gemm_tc<<<dim3(3 * EMBD / 128, M_TOTAL / 128), 256, gemm_smem>>>(
        xrbuf, wtq, qkv_b, 0, qbuf, outK, outV, kpbuf);

    // 2) causal flash attention (permuted Q/K, canonical V)
    flash_tc<<<dim3(SEQ / 128, BATCH * N_HEAD), 256, flash_smem>>>(
        qbuf, kpbuf, outV, abuf);

    // 3) output projection (permuted A and B; canonical output)
    gemm_tc<<<dim3(EMBD / 128, M_TOTAL / 128), 256, gemm_smem>>>(
        abuf, wtp, proj_b, 1, out, nullptr, nullptr, nullptr);
}

// round 6
// speedup vs baseline: 5.7710x; 1.6848x over previous
#include <cuda_runtime.h>
#include <cuda_fp16.h>
#include <math.h>
#include <stdint.h>

#define N_HEAD   16
#define HEAD_DIM 64
#define EMBD     1024
#define BATCH    2
#define SEQ      2048
#define M_TOTAL  (BATCH*SEQ)   // 4096

// ---------------- scratch (device globals; no allocs allowed) ---------------
__device__ __half g_qh[(size_t)BATCH*N_HEAD*SEQ*HEAD_DIM];   // Q fp16 [B,H,S,D]
__device__ __half g_kh[(size_t)BATCH*N_HEAD*SEQ*HEAD_DIM];   // K fp16 copy
__device__ __half g_vh[(size_t)BATCH*N_HEAD*SEQ*HEAD_DIM];   // V fp16 copy
__device__ __half g_ah[(size_t)M_TOTAL*EMBD];                // attn out fp16 [B*S,E]
__device__ __half g_xh[(size_t)M_TOTAL*EMBD];                // x fp16
__device__ __half g_wqkvh[(size_t)3*EMBD*EMBD];              // W_qkv^T fp16 [3072,1024]
__device__ __half g_wprojh[(size_t)EMBD*EMBD];               // W_proj^T fp16 [1024,1024]

// ---------------- helpers ---------------------------------------------------
__device__ __forceinline__ uint32_t smem_u32(const void* p) {
    uint32_t a;
    asm("{ .reg .u64 t; cvta.to.shared.u64 t, %1; cvt.u32.u64 %0, t; }" : "=r"(a) : "l"(p));
    return a;
}
__device__ __forceinline__ uint32_t packh2(float x, float y) {
    __half2 h = __floats2half2_rn(x, y);
    return *(uint32_t*)&h;
}
__device__ __forceinline__ void mma_f16(float* c, const uint32_t* a, const uint32_t* b) {
    asm volatile("mma.sync.aligned.m16n8k16.row.col.f32.f16.f16.f32 "
        "{%0,%1,%2,%3}, {%4,%5,%6,%7}, {%8,%9}, {%0,%1,%2,%3};"
        : "+f"(c[0]), "+f"(c[1]), "+f"(c[2]), "+f"(c[3])
        : "r"(a[0]), "r"(a[1]), "r"(a[2]), "r"(a[3]), "r"(b[0]), "r"(b[1]));
}
__device__ __forceinline__ void ldm_x4(uint32_t* r, uint32_t addr) {
    asm volatile("ldmatrix.sync.aligned.m8n8.x4.shared.b16 {%0,%1,%2,%3}, [%4];"
        : "=r"(r[0]), "=r"(r[1]), "=r"(r[2]), "=r"(r[3]) : "r"(addr));
}
__device__ __forceinline__ void ldm_x4_t(uint32_t* r, uint32_t addr) {
    asm volatile("ldmatrix.sync.aligned.m8n8.x4.trans.shared.b16 {%0,%1,%2,%3}, [%4];"
        : "=r"(r[0]), "=r"(r[1]), "=r"(r[2]), "=r"(r[3]) : "r"(addr));
}
__device__ __forceinline__ void cp16(void* dst_smem, const void* src) {
    uint32_t d = smem_u32(dst_smem);
    asm volatile("cp.async.cg.shared.global [%0], [%1], 16;" :: "r"(d), "l"(src) : "memory");
}
#define CP_COMMIT() asm volatile("cp.async.commit_group;" ::: "memory")
#define CP_WAIT(n)  asm volatile("cp.async.wait_group %0;" :: "n"(n) : "memory")

// ---------------- prep kernels ----------------------------------------------
__global__ __launch_bounds__(256)
void to_half_kernel(const float* __restrict__ x, __half* __restrict__ y, int n8)
{
    int i = blockIdx.x * blockDim.x + threadIdx.x;
    if (i < n8) {
        float4 a = ((const float4*)x)[2 * i];
        float4 b = ((const float4*)x)[2 * i + 1];
        uint4 o;
        o.x = packh2(a.x, a.y); o.y = packh2(a.z, a.w);
        o.z = packh2(b.x, b.y); o.w = packh2(b.z, b.w);
        ((uint4*)y)[i] = o;
    }
}

// Transpose W [1024, N] -> WT [N, 1024] fp16
__global__ __launch_bounds__(256)
void transpose_half_kernel(const float* __restrict__ W, __half* __restrict__ WT, int N)
{
    __shared__ float t[32][33];
    int n0 = blockIdx.x * 32, k0 = blockIdx.y * 32;
    int tx = threadIdx.x, ty = threadIdx.y;
#pragma unroll
    for (int i = 0; i < 4; i++)
        t[ty + 8 * i][tx] = W[(size_t)(k0 + ty + 8 * i) * N + n0 + tx];
    __syncthreads();
#pragma unroll
    for (int i = 0; i < 4; i++)
        WT[(size_t)(n0 + ty + 8 * i) * EMBD + k0 + tx] = __float2half(t[tx][ty + 8 * i]);
}

// ---------------- fp16 mma.sync GEMM ----------------------------------------
// C[M,Ntot] = A[M,1024] @ Bt^T + bias.  A,[Ntot,1024] Bt fp16 K-contig.
// Block 128x128, BK=32. 8 warps, each 32(M)x64(N). 2-stage cp.async.
#define GSH 72       // smem stride (halves): 144B, 8-row ldmatrix phases conflict-free
#define GKT (EMBD/32)

__global__ __launch_bounds__(256)
void gemm_tc(const __half* __restrict__ A, const __half* __restrict__ Bt,
             const float* __restrict__ bias, int mode,
             float* __restrict__ o0, float* __restrict__ o1, float* __restrict__ o2,
             __half* __restrict__ h0, __half* __restrict__ h1, __half* __restrict__ h2)
{
    extern __shared__ __half smg[];
    __half* SA = smg;                      // [2][128*GSH]
    __half* SB = smg + 2 * 128 * GSH;      // [2][128*GSH]

    const int tid = threadIdx.x, wid = tid >> 5, lane = tid & 31;
    const int g = lane >> 2, t4 = lane & 3;
    const int wm = wid >> 1, wn = wid & 1;
    const int m0 = blockIdx.y * 128, n0 = blockIdx.x * 128;
    const __half* Ab = A  + (size_t)m0 * EMBD;
    const __half* Bb = Bt + (size_t)n0 * EMBD;

    float c[2][8][4];
#pragma unroll
    for (int mt = 0; mt < 2; mt++)
#pragma unroll
        for (int nt = 0; nt < 8; nt++)
#pragma unroll
            for (int e = 0; e < 4; e++) c[mt][nt][e] = 0.f;

    auto load_tile = [&](int t) {
        __half* as = SA + (t & 1) * 128 * GSH;
        __half* bs = SB + (t & 1) * 128 * GSH;
        int kt = t * 32;
        // 128 rows x 32 halves (64B) = 4 chunks/row; 512 chunks/operand, 2/thread
#pragma unroll
        for (int i = 0; i < 2; i++) {
            int idx = tid + i * 256;
            int r = idx >> 2, ch = idx & 3;
            cp16(as + r * GSH + ch * 8, Ab + (size_t)r * EMBD + kt + ch * 8);
        }
#pragma unroll
        for (int i = 0; i < 2; i++) {
            int idx = tid + i * 256;
            int r = idx >> 2, ch = idx & 3;
            cp16(bs + r * GSH + ch * 8, Bb + (size_t)r * EMBD + kt + ch * 8);
        }
    };

    load_tile(0); CP_COMMIT();

    // ldmatrix lane->address components (halves)
    const int a_row = (lane & 15), a_off = (lane >> 4) * 8;
    const int b_row = ((lane >> 4) & 1) * 8 + (lane & 7), b_off = ((lane >> 3) & 1) * 8;

    for (int t = 0; t < GKT; t++) {
        CP_WAIT(0);
        __syncthreads();
        if (t + 1 < GKT) { load_tile(t + 1); CP_COMMIT(); }
        uint32_t sa = smem_u32(SA + (t & 1) * 128 * GSH);
        uint32_t sb = smem_u32(SB + (t & 1) * 128 * GSH);
#pragma unroll
        for (int ks = 0; ks < 2; ks++) {
            int k0 = ks * 16;
            uint32_t a[2][4], b[4][4];
#pragma unroll
            for (int mt = 0; mt < 2; mt++)
                ldm_x4(a[mt], sa + 2 * ((wm * 32 + mt * 16 + a_row) * GSH + k0 + a_off));
#pragma unroll
            for (int ng = 0; ng < 4; ng++)
                ldm_x4(b[ng], sb + 2 * ((wn * 64 + ng * 16 + b_row) * GSH + k0 + b_off));
#pragma unroll
            for (int mt = 0; mt < 2; mt++)
#pragma unroll
                for (int ng = 0; ng < 4; ng++) {
                    mma_f16(c[mt][2 * ng],     a[mt], b[ng]);
                    mma_f16(c[mt][2 * ng + 1], a[mt], b[ng] + 2);
                }
        }
        __syncthreads();
    }

    // epilogue: C layout c0,c1 = row g cols 2t4,2t4+1; c2,c3 = row g+8
#pragma unroll
    for (int mt = 0; mt < 2; mt++) {
#pragma unroll
        for (int nt = 0; nt < 8; nt++) {
            int row0 = m0 + wm * 32 + mt * 16 + g;
            int row1 = row0 + 8;
            int col  = n0 + wn * 64 + nt * 8 + 2 * t4;
            float b0 = bias[col], b1 = bias[col + 1];
            float2 v0 = make_float2(c[mt][nt][0] + b0, c[mt][nt][1] + b1);
            float2 v1 = make_float2(c[mt][nt][2] + b0, c[mt][nt][3] + b1);
            if (mode == 0) {
                int sec = col >> 10, nn = col & 1023;
                int h = nn >> 6, d = nn & 63;
                int b_0 = row0 >> 11, s_0 = row0 & 2047;
                int b_1 = row1 >> 11, s_1 = row1 & 2047;
                size_t i0 = (((size_t)(b_0 * N_HEAD + h) * SEQ + s_0) << 6) + d;
                size_t i1 = (((size_t)(b_1 * N_HEAD + h) * SEQ + s_1) << 6) + d;
                if (sec == 0) {           // Q: fp16 scratch only
                    *(uint32_t*)&h0[i0] = packh2(v0.x, v0.y);
                    *(uint32_t*)&h0[i1] = packh2(v1.x, v1.y);
                } else if (sec == 1) {    // K: fp32 canonical + fp16 scratch
                    *(float2*)&o1[i0] = v0;
                    *(float2*)&o1[i1] = v1;
                    *(uint32_t*)&h1[i0] = packh2(v0.x, v0.y);
                    *(uint32_t*)&h1[i1] = packh2(v1.x, v1.y);
                } else {                  // V: fp32 canonical + fp16 scratch
                    *(float2*)&o2[i0] = v0;
                    *(float2*)&o2[i1] = v1;
                    *(uint32_t*)&h2[i0] = packh2(v0.x, v0.y);
                    *(uint32_t*)&h2[i1] = packh2(v1.x, v1.y);
                }
            } else {
                *(float2*)&o0[(size_t)row0 * EMBD + col] = v0;
                *(float2*)&o0[(size_t)row1 * EMBD + col] = v1;
            }
        }
    }
}

// ---------------- flash attention (fp16 mma + ldmatrix) ---------------------
// Block: 128 queries x one (b,h); 8 warps, warp = 16 rows x full 64 cols.
#define FSH 72

__global__ __launch_bounds__(256)
void flash_tc(const __half* __restrict__ q, const __half* __restrict__ k,
              const __half* __restrict__ v, __half* __restrict__ out)
{
    extern __shared__ __half smf[];
    __half* Qs = smf;                    // [128][FSH]
    __half* Ks = smf + 128 * FSH;        // [2][64][FSH]
    __half* Vs = Ks + 2 * 64 * FSH;      // [2][64][FSH]

    const int tid = threadIdx.x, wid = tid >> 5, lane = tid & 31;
    const int g = lane >> 2, t4 = lane & 3;
    const int qb = gridDim.x - 1 - blockIdx.x;   // big causal blocks first
    const int bh = blockIdx.y;
    const int q0 = qb * 128;
    const size_t base = (size_t)bh * SEQ * HEAD_DIM;
    const int qw = q0 + wid * 16;
    const int jtmax = 2 * qb + 1;

    auto load_kv = [&](int jt) {
        __half* kd = Ks + (jt & 1) * 64 * FSH;
        __half* vd = Vs + (jt & 1) * 64 * FSH;
        const __half* kg = k + base + (size_t)jt * 64 * 64;
        const __half* vg = v + base + (size_t)jt * 64 * 64;
        // 64 rows x 64 halves (128B) = 8 chunks/row; 512 chunks/operand, 2/thread
#pragma unroll
        for (int i = 0; i < 2; i++) {
            int idx = tid + i * 256;
            int r = idx >> 3, ch = idx & 7;
            cp16(kd + r * FSH + ch * 8, kg + (size_t)r * 64 + ch * 8);
            cp16(vd + r * FSH + ch * 8, vg + (size_t)r * 64 + ch * 8);
        }
    };

#pragma unroll
    for (int i = 0; i < 4; i++) {
        int idx = tid + i * 256;
        int r = idx >> 3, ch = idx & 7;
        cp16(Qs + r * FSH + ch * 8, q + base + (size_t)(q0 + r) * 64 + ch * 8);
    }
    load_kv(0);
    CP_COMMIT();

    float mr[2] = {-1e30f, -1e30f}, lr[2] = {0.f, 0.f};
    float o[8][4];
#pragma unroll
    for (int nt = 0; nt < 8; nt++)
#pragma unroll
        for (int e = 0; e < 4; e++) o[nt][e] = 0.f;

    const int a_row = (lane & 15), a_off = (lane >> 4) * 8;
    const int b_row = ((lane >> 4) & 1) * 8 + (lane & 7), b_off = ((lane >> 3) & 1) * 8;
    const int v_row = ((lane >> 3) & 1) * 8 + (lane & 7), v_off = (lane >> 4) * 8;

    for (int jt = 0; jt <= jtmax; jt++) {
        if (jt < jtmax) { load_kv(jt + 1); CP_COMMIT(); CP_WAIT(1); }
        else            { CP_WAIT(0); }
        __syncthreads();
        uint32_t kb = smem_u32(Ks + (jt & 1) * 64 * FSH);
        uint32_t vb = smem_u32(Vs + (jt & 1) * 64 * FSH);
        uint32_t qsb = smem_u32(Qs);

        if (jt * 64 <= qw + 15) {
            // ---- S = Q K^T : 4 k16 steps over d=64 ----
            float s[8][4];
#pragma unroll
            for (int nt = 0; nt < 8; nt++)
#pragma unroll
                for (int e = 0; e < 4; e++) s[nt][e] = 0.f;
#pragma unroll
            for (int ks = 0; ks < 4; ks++) {
                int k0 = ks * 16;
                uint32_t aq[4], bk[4][4];
                ldm_x4(aq, qsb + 2 * ((wid * 16 + a_row) * FSH + k0 + a_off));
#pragma unroll
                for (int ng = 0; ng < 4; ng++)
                    ldm_x4(bk[ng], kb + 2 * ((ng * 16 + b_row) * FSH + k0 + b_off));
#pragma unroll
                for (int ng = 0; ng < 4; ng++) {
                    mma_f16(s[2 * ng],     aq, bk[ng]);
                    mma_f16(s[2 * ng + 1], aq, bk[ng] + 2);
                }
            }
            // ---- scale + causal mask ----
            bool diag = (jt * 64 + 63 > qw);
#pragma unroll
            for (int nt = 0; nt < 8; nt++) {
                int colb = jt * 64 + nt * 8 + 2 * t4;
#pragma unroll
                for (int e = 0; e < 4; e++) {
                    int row = qw + g + (e >> 1) * 8;
                    int col = colb + (e & 1);
                    s[nt][e] *= 0.125f;
                    if (diag && col > row) s[nt][e] = -1e30f;
                }
            }
            // ---- online softmax (rows in quad: shfl 1,2) ----
            float mx0 = -1e30f, mx1 = -1e30f;
#pragma unroll
            for (int nt = 0; nt < 8; nt++) {
                mx0 = fmaxf(mx0, fmaxf(s[nt][0], s[nt][1]));
                mx1 = fmaxf(mx1, fmaxf(s[nt][2], s[nt][3]));
            }
            mx0 = fmaxf(mx0, __shfl_xor_sync(0xffffffffu, mx0, 1));
            mx0 = fmaxf(mx0, __shfl_xor_sync(0xffffffffu, mx0, 2));
            mx1 = fmaxf(mx1, __shfl_xor_sync(0xffffffffu, mx1, 1));
            mx1 = fmaxf(mx1, __shfl_xor_sync(0xffffffffu, mx1, 2));
            float mn0 = fmaxf(mr[0], mx0), mn1 = fmaxf(mr[1], mx1);
            float al0 = __expf(mr[0] - mn0), al1 = __expf(mr[1] - mn1);
            mr[0] = mn0; mr[1] = mn1;
            float sum0 = 0.f, sum1 = 0.f;
#pragma unroll
            for (int nt = 0; nt < 8; nt++) {
                s[nt][0] = __expf(s[nt][0] - mn0); sum0 += s[nt][0];
                s[nt][1] = __expf(s[nt][1] - mn0); sum0 += s[nt][1];
                s[nt][2] = __expf(s[nt][2] - mn1); sum1 += s[nt][2];
                s[nt][3] = __expf(s[nt][3] - mn1); sum1 += s[nt][3];
            }
            sum0 += __shfl_xor_sync(0xffffffffu, sum0, 1);
            sum0 += __shfl_xor_sync(0xffffffffu, sum0, 2);
            sum1 += __shfl_xor_sync(0xffffffffu, sum1, 1);
            sum1 += __shfl_xor_sync(0xffffffffu, sum1, 2);
            lr[0] = lr[0] * al0 + sum0;
            lr[1] = lr[1] * al1 + sum1;
#pragma unroll
            for (int nt = 0; nt < 8; nt++) {
                o[nt][0] *= al0; o[nt][1] *= al0;
                o[nt][2] *= al1; o[nt][3] *= al1;
            }
            // ---- O += P V : P packed straight from S C-frags ----
#pragma unroll
            for (int j = 0; j < 4; j++) {          // key group of 16
                uint32_t ap[4];
                ap[0] = packh2(s[2 * j][0],     s[2 * j][1]);
                ap[1] = packh2(s[2 * j][2],     s[2 * j][3]);
                ap[2] = packh2(s[2 * j + 1][0], s[2 * j + 1][1]);
                ap[3] = packh2(s[2 * j + 1][2], s[2 * j + 1][3]);
#pragma unroll
                for (int np = 0; np < 4; np++) {   // d group of 16
                    uint32_t bv[4];
                    ldm_x4_t(bv, vb + 2 * ((16 * j + v_row) * FSH + np * 16 + v_off));
                    mma_f16(o[2 * np],     ap, bv);
                    mma_f16(o[2 * np + 1], ap, bv + 2);
                }
            }
        }
        __syncthreads();
    }

    // ---- normalize + store fp16 (A operand of proj GEMM) ----
    int b_ = bh >> 4, h = bh & 15;
    float i0 = 1.f / lr[0], i1 = 1.f / lr[1];
#pragma unroll
    for (int nt = 0; nt < 8; nt++) {
        int d = h * 64 + nt * 8 + 2 * t4;
        int r0 = qw + g, r1 = qw + 8 + g;
        *(uint32_t*)&out[(size_t)(b_ * SEQ + r0) * EMBD + d] = packh2(o[nt][0] * i0, o[nt][1] * i0);
        *(uint32_t*)&out[(size_t)(b_ * SEQ + r1) * EMBD + d] = packh2(o[nt][2] * i1, o[nt][3] * i1);
    }
}

// ---------------------------------------------------------------------------
extern "C" void kernel_launch(void* const* d_in, const int* in_sizes, int n_in,
                              void* d_out, int out_size)
{
    const float* x      = (const float*)d_in[0];
    const float* qkv_w  = (const float*)d_in[1];
    const float* qkv_b  = (const float*)d_in[2];
    const float* proj_w = (const float*)d_in[3];
    const float* proj_b = (const float*)d_in[4];

    float* out  = (float*)d_out;
    float* outK = out  + (size_t)BATCH * SEQ * EMBD;
    float* outV = outK + (size_t)BATCH * SEQ * EMBD;

    __half *qh, *kh, *vh, *ah, *xh, *wqh, *wph;
    cudaGetSymbolAddress((void**)&qh,  g_qh);
    cudaGetSymbolAddress((void**)&kh,  g_kh);
    cudaGetSymbolAddress((void**)&vh,  g_vh);
    cudaGetSymbolAddress((void**)&ah,  g_ah);
    cudaGetSymbolAddress((void**)&xh,  g_xh);
    cudaGetSymbolAddress((void**)&wqh, g_wqkvh);
    cudaGetSymbolAddress((void**)&wph, g_wprojh);

    const int gemm_smem  = 2 * 2 * 128 * GSH * (int)sizeof(__half);           // 73728
    const int flash_smem = (128 * FSH + 4 * 64 * FSH) * (int)sizeof(__half);  // 55296
    cudaFuncSetAttribute(gemm_tc,
                         cudaFuncAttributeMaxDynamicSharedMemorySize, gemm_smem);
    cudaFuncSetAttribute(flash_tc,
                         cudaFuncAttributeMaxDynamicSharedMemorySize, flash_smem);

    // 0) prep: convert x and transposed weights to fp16
    to_half_kernel<<<(M_TOTAL * EMBD / 8 + 255) / 256, 256>>>(x, xh, M_TOTAL * EMBD / 8);
    transpose_half_kernel<<<dim3(3 * EMBD / 32, EMBD / 32), dim3(32, 8)>>>(qkv_w, wqh, 3 * EMBD);
    transpose_half_kernel<<<dim3(EMBD / 32, EMBD / 32), dim3(32, 8)>>>(proj_w, wph, EMBD);

    // 1) QKV GEMM -> Q fp16; K,V fp32 canonical + fp16 scratch
    gemm_tc<<<dim3(3 * EMBD / 128, M_TOTAL / 128), 256, gemm_smem>>>(
        xh, wqh, qkv_b, 0, nullptr, outK, outV, qh, kh, vh);

    // 2) causal flash attention (fp16 tensor cores)
    flash_tc<<<dim3(SEQ / 128, BATCH * N_HEAD), 256, flash_smem>>>(
        qh, kh, vh, ah);

    // 3) output projection (fp16 in, fp32 out)
    gemm_tc<<<dim3(EMBD / 128, M_TOTAL / 128), 256, gemm_smem>>>(
        ah, wph, proj_b, 1, out, nullptr, nullptr, nullptr, nullptr, nullptr);
}

// round 7
// speedup vs baseline: 5.9881x; 1.0376x over previous
#include <cuda_runtime.h>
#include <cuda_fp16.h>
#include <math.h>
#include <stdint.h>

#define N_HEAD   16
#define HEAD_DIM 64
#define EMBD     1024
#define BATCH    2
#define SEQ      2048
#define M_TOTAL  (BATCH*SEQ)   // 4096

// ---------------- scratch (device globals; no allocs allowed) ---------------
__device__ __half g_qh[(size_t)BATCH*N_HEAD*SEQ*HEAD_DIM];   // Q fp16 [B,H,S,D]
__device__ __half g_kh[(size_t)BATCH*N_HEAD*SEQ*HEAD_DIM];   // K fp16 copy
__device__ __half g_vh[(size_t)BATCH*N_HEAD*SEQ*HEAD_DIM];   // V fp16 copy
__device__ __half g_ah[(size_t)M_TOTAL*EMBD];                // attn out fp16 [B*S,E]
__device__ __half g_xh[(size_t)M_TOTAL*EMBD];                // x fp16
__device__ __half g_wqkvh[(size_t)3*EMBD*EMBD];              // W_qkv^T fp16 [3072,1024]
__device__ __half g_wprojh[(size_t)EMBD*EMBD];               // W_proj^T fp16 [1024,1024]

// ---------------- helpers ---------------------------------------------------
__device__ __forceinline__ uint32_t smem_u32(const void* p) {
    uint32_t a;
    asm("{ .reg .u64 t; cvta.to.shared.u64 t, %1; cvt.u32.u64 %0, t; }" : "=r"(a) : "l"(p));
    return a;
}
__device__ __forceinline__ uint32_t packh2(float x, float y) {
    __half2 h = __floats2half2_rn(x, y);
    return *(uint32_t*)&h;
}
__device__ __forceinline__ void mma_f16(float* c, const uint32_t* a, const uint32_t* b) {
    asm volatile("mma.sync.aligned.m16n8k16.row.col.f32.f16.f16.f32 "
        "{%0,%1,%2,%3}, {%4,%5,%6,%7}, {%8,%9}, {%0,%1,%2,%3};"
        : "+f"(c[0]), "+f"(c[1]), "+f"(c[2]), "+f"(c[3])
        : "r"(a[0]), "r"(a[1]), "r"(a[2]), "r"(a[3]), "r"(b[0]), "r"(b[1]));
}
__device__ __forceinline__ void ldm_x4(uint32_t* r, uint32_t addr) {
    asm volatile("ldmatrix.sync.aligned.m8n8.x4.shared.b16 {%0,%1,%2,%3}, [%4];"
        : "=r"(r[0]), "=r"(r[1]), "=r"(r[2]), "=r"(r[3]) : "r"(addr));
}
__device__ __forceinline__ void ldm_x4_t(uint32_t* r, uint32_t addr) {
    asm volatile("ldmatrix.sync.aligned.m8n8.x4.trans.shared.b16 {%0,%1,%2,%3}, [%4];"
        : "=r"(r[0]), "=r"(r[1]), "=r"(r[2]), "=r"(r[3]) : "r"(addr));
}
__device__ __forceinline__ void cp16(void* dst_smem, const void* src) {
    uint32_t d = smem_u32(dst_smem);
    asm volatile("cp.async.cg.shared.global [%0], [%1], 16;" :: "r"(d), "l"(src) : "memory");
}
#define CP_COMMIT() asm volatile("cp.async.commit_group;" ::: "memory")
#define CP_WAIT(n)  asm volatile("cp.async.wait_group %0;" :: "n"(n) : "memory")

// ---------------- prep kernels ----------------------------------------------
__global__ __launch_bounds__(256)
void to_half_kernel(const float* __restrict__ x, __half* __restrict__ y, int n8)
{
    int i = blockIdx.x * blockDim.x + threadIdx.x;
    if (i < n8) {
        float4 a = ((const float4*)x)[2 * i];
        float4 b = ((const float4*)x)[2 * i + 1];
        uint4 o;
        o.x = packh2(a.x, a.y); o.y = packh2(a.z, a.w);
        o.z = packh2(b.x, b.y); o.w = packh2(b.z, b.w);
        ((uint4*)y)[i] = o;
    }
}

// Transpose W [1024, N] -> WT [N, 1024] fp16
__global__ __launch_bounds__(256)
void transpose_half_kernel(const float* __restrict__ W, __half* __restrict__ WT, int N)
{
    __shared__ float t[32][33];
    int n0 = blockIdx.x * 32, k0 = blockIdx.y * 32;
    int tx = threadIdx.x, ty = threadIdx.y;
#pragma unroll
    for (int i = 0; i < 4; i++)
        t[ty + 8 * i][tx] = W[(size_t)(k0 + ty + 8 * i) * N + n0 + tx];
    __syncthreads();
#pragma unroll
    for (int i = 0; i < 4; i++)
        WT[(size_t)(n0 + ty + 8 * i) * EMBD + k0 + tx] = __float2half(t[tx][ty + 8 * i]);
}

// ---------------- fp16 mma.sync GEMM ----------------------------------------
// C[M,Ntot] = A[M,1024] @ Bt^T + bias.  Block 128x128, BK=64, 3-stage cp.async
// with ONE barrier per K-tile (write distance 3 protects buffer reuse).
// 8 warps, each 32(M)x64(N).
#define GSH 72       // stride (halves) = 144B: 64 data + 8 pad; ldmatrix conflict-free
#define GKT (EMBD/64)

__global__ __launch_bounds__(256)
void gemm_tc(const __half* __restrict__ A, const __half* __restrict__ Bt,
             const float* __restrict__ bias, int mode,
             float* __restrict__ o0, float* __restrict__ o1, float* __restrict__ o2,
             __half* __restrict__ h0, __half* __restrict__ h1, __half* __restrict__ h2)
{
    extern __shared__ __half smg[];
    __half* SA = smg;                      // [3][128*GSH]
    __half* SB = smg + 3 * 128 * GSH;      // [3][128*GSH]

    const int tid = threadIdx.x, wid = tid >> 5, lane = tid & 31;
    const int g = lane >> 2, t4 = lane & 3;
    const int wm = wid >> 1, wn = wid & 1;
    const int m0 = blockIdx.y * 128, n0 = blockIdx.x * 128;
    const __half* Ab = A  + (size_t)m0 * EMBD;
    const __half* Bb = Bt + (size_t)n0 * EMBD;

    float c[2][8][4];
#pragma unroll
    for (int mt = 0; mt < 2; mt++)
#pragma unroll
        for (int nt = 0; nt < 8; nt++)
#pragma unroll
            for (int e = 0; e < 4; e++) c[mt][nt][e] = 0.f;

    auto load_tile = [&](int t) {
        __half* as = SA + (t % 3) * 128 * GSH;
        __half* bs = SB + (t % 3) * 128 * GSH;
        int kt = t * 64;
        // 128 rows x 64 halves (128B) = 8 chunks/row; 1024 chunks/op, 4/thread
#pragma unroll
        for (int i = 0; i < 4; i++) {
            int idx = tid + i * 256;
            int r = idx >> 3, ch = idx & 7;
            cp16(as + r * GSH + ch * 8, Ab + (size_t)r * EMBD + kt + ch * 8);
        }
#pragma unroll
        for (int i = 0; i < 4; i++) {
            int idx = tid + i * 256;
            int r = idx >> 3, ch = idx & 7;
            cp16(bs + r * GSH + ch * 8, Bb + (size_t)r * EMBD + kt + ch * 8);
        }
    };

    load_tile(0); CP_COMMIT();
    load_tile(1); CP_COMMIT();

    // ldmatrix lane->address components (halves)
    const int a_row = (lane & 15), a_off = (lane >> 4) * 8;
    const int b_row = ((lane >> 4) & 1) * 8 + (lane & 7), b_off = ((lane >> 3) & 1) * 8;

    for (int t = 0; t < GKT; t++) {
        CP_WAIT(1);            // tile t resident (t+1 may be in flight)
        __syncthreads();       // all warps done iter t-1 (buf (t+2)%3 now writable)
        if (t + 2 < GKT) { load_tile(t + 2); CP_COMMIT(); }
        else             { CP_COMMIT(); }    // empty group keeps wait counts exact
        uint32_t sa = smem_u32(SA + (t % 3) * 128 * GSH);
        uint32_t sb = smem_u32(SB + (t % 3) * 128 * GSH);
#pragma unroll
        for (int ks = 0; ks < 4; ks++) {
            int k0 = ks * 16;
            uint32_t a[2][4], b[4][4];
#pragma unroll
            for (int mt = 0; mt < 2; mt++)
                ldm_x4(a[mt], sa + 2 * ((wm * 32 + mt * 16 + a_row) * GSH + k0 + a_off));
#pragma unroll
            for (int ng = 0; ng < 4; ng++)
                ldm_x4(b[ng], sb + 2 * ((wn * 64 + ng * 16 + b_row) * GSH + k0 + b_off));
#pragma unroll
            for (int mt = 0; mt < 2; mt++)
#pragma unroll
                for (int ng = 0; ng < 4; ng++) {
                    mma_f16(c[mt][2 * ng],     a[mt], b[ng]);
                    mma_f16(c[mt][2 * ng + 1], a[mt], b[ng] + 2);
                }
        }
    }

    // epilogue: c0,c1 = row g cols 2t4,2t4+1; c2,c3 = row g+8
#pragma unroll
    for (int mt = 0; mt < 2; mt++) {
#pragma unroll
        for (int nt = 0; nt < 8; nt++) {
            int row0 = m0 + wm * 32 + mt * 16 + g;
            int row1 = row0 + 8;
            int col  = n0 + wn * 64 + nt * 8 + 2 * t4;
            float b0 = bias[col], b1 = bias[col + 1];
            float2 v0 = make_float2(c[mt][nt][0] + b0, c[mt][nt][1] + b1);
            float2 v1 = make_float2(c[mt][nt][2] + b0, c[mt][nt][3] + b1);
            if (mode == 0) {
                int sec = col >> 10, nn = col & 1023;
                int h = nn >> 6, d = nn & 63;
                int b_0 = row0 >> 11, s_0 = row0 & 2047;
                int b_1 = row1 >> 11, s_1 = row1 & 2047;
                size_t i0 = (((size_t)(b_0 * N_HEAD + h) * SEQ + s_0) << 6) + d;
                size_t i1 = (((size_t)(b_1 * N_HEAD + h) * SEQ + s_1) << 6) + d;
                if (sec == 0) {           // Q: fp16 scratch only
                    *(uint32_t*)&h0[i0] = packh2(v0.x, v0.y);
                    *(uint32_t*)&h0[i1] = packh2(v1.x, v1.y);
                } else if (sec == 1) {    // K: fp32 canonical + fp16 scratch
                    *(float2*)&o1[i0] = v0;
                    *(float2*)&o1[i1] = v1;
                    *(uint32_t*)&h1[i0] = packh2(v0.x, v0.y);
                    *(uint32_t*)&h1[i1] = packh2(v1.x, v1.y);
                } else {                  // V: fp32 canonical + fp16 scratch
                    *(float2*)&o2[i0] = v0;
                    *(float2*)&o2[i1] = v1;
                    *(uint32_t*)&h2[i0] = packh2(v0.x, v0.y);
                    *(uint32_t*)&h2[i1] = packh2(v1.x, v1.y);
                }
            } else {
                *(float2*)&o0[(size_t)row0 * EMBD + col] = v0;
                *(float2*)&o0[(size_t)row1 * EMBD + col] = v1;
            }
        }
    }
}

// ---------------- flash attention (fp16 mma + ldmatrix, 3-stage KV) ---------
// Block: 128 queries x one (b,h); 8 warps, warp = 16 rows x full 64 cols.
// One barrier per KV tile: 3-stage ring, write distance 3.
#define FSH 72

__global__ __launch_bounds__(256)
void flash_tc(const __half* __restrict__ q, const __half* __restrict__ k,
              const __half* __restrict__ v, __half* __restrict__ out)
{
    extern __shared__ __half smf[];
    __half* Qs = smf;                    // [128][FSH]
    __half* Ks = smf + 128 * FSH;        // [3][64][FSH]
    __half* Vs = Ks + 3 * 64 * FSH;      // [3][64][FSH]

    const int tid = threadIdx.x, wid = tid >> 5, lane = tid & 31;
    const int g = lane >> 2, t4 = lane & 3;
    const int qb = gridDim.x - 1 - blockIdx.x;   // big causal blocks first
    const int bh = blockIdx.y;
    const int q0 = qb * 128;
    const size_t base = (size_t)bh * SEQ * HEAD_DIM;
    const int qw = q0 + wid * 16;
    const int jtmax = 2 * qb + 1;

    auto load_kv = [&](int jt) {
        __half* kd = Ks + (jt % 3) * 64 * FSH;
        __half* vd = Vs + (jt % 3) * 64 * FSH;
        const __half* kg = k + base + (size_t)jt * 64 * 64;
        const __half* vg = v + base + (size_t)jt * 64 * 64;
#pragma unroll
        for (int i = 0; i < 2; i++) {
            int idx = tid + i * 256;
            int r = idx >> 3, ch = idx & 7;
            cp16(kd + r * FSH + ch * 8, kg + (size_t)r * 64 + ch * 8);
            cp16(vd + r * FSH + ch * 8, vg + (size_t)r * 64 + ch * 8);
        }
    };

    // group 0: Q tile + KV tile 0; group 1: KV tile 1
#pragma unroll
    for (int i = 0; i < 4; i++) {
        int idx = tid + i * 256;
        int r = idx >> 3, ch = idx & 7;
        cp16(Qs + r * FSH + ch * 8, q + base + (size_t)(q0 + r) * 64 + ch * 8);
    }
    load_kv(0); CP_COMMIT();
    load_kv(1); CP_COMMIT();

    float mr[2] = {-1e30f, -1e30f}, lr[2] = {0.f, 0.f};
    float o[8][4];
#pragma unroll
    for (int nt = 0; nt < 8; nt++)
#pragma unroll
        for (int e = 0; e < 4; e++) o[nt][e] = 0.f;

    const int a_row = (lane & 15), a_off = (lane >> 4) * 8;
    const int b_row = ((lane >> 4) & 1) * 8 + (lane & 7), b_off = ((lane >> 3) & 1) * 8;
    const int v_row = ((lane >> 3) & 1) * 8 + (lane & 7), v_off = (lane >> 4) * 8;

    for (int jt = 0; jt <= jtmax; jt++) {
        CP_WAIT(1);            // KV tile jt resident
        __syncthreads();       // all warps done tile jt-1 (buf (jt+2)%3 writable)
        if (jt + 2 <= jtmax) { load_kv(jt + 2); CP_COMMIT(); }
        else                 { CP_COMMIT(); }
        uint32_t kb = smem_u32(Ks + (jt % 3) * 64 * FSH);
        uint32_t vb = smem_u32(Vs + (jt % 3) * 64 * FSH);
        uint32_t qsb = smem_u32(Qs);

        if (jt * 64 <= qw + 15) {
            // ---- S = Q K^T : 4 k16 steps over d=64 ----
            float s[8][4];
#pragma unroll
            for (int nt = 0; nt < 8; nt++)
#pragma unroll
                for (int e = 0; e < 4; e++) s[nt][e] = 0.f;
#pragma unroll
            for (int ks = 0; ks < 4; ks++) {
                int k0 = ks * 16;
                uint32_t aq[4], bk[4][4];
                ldm_x4(aq, qsb + 2 * ((wid * 16 + a_row) * FSH + k0 + a_off));
#pragma unroll
                for (int ng = 0; ng < 4; ng++)
                    ldm_x4(bk[ng], kb + 2 * ((ng * 16 + b_row) * FSH + k0 + b_off));
#pragma unroll
                for (int ng = 0; ng < 4; ng++) {
                    mma_f16(s[2 * ng],     aq, bk[ng]);
                    mma_f16(s[2 * ng + 1], aq, bk[ng] + 2);
                }
            }
            // ---- scale + causal mask ----
            bool diag = (jt * 64 + 63 > qw);
#pragma unroll
            for (int nt = 0; nt < 8; nt++) {
                int colb = jt * 64 + nt * 8 + 2 * t4;
#pragma unroll
                for (int e = 0; e < 4; e++) {
                    int row = qw + g + (e >> 1) * 8;
                    int col = colb + (e & 1);
                    s[nt][e] *= 0.125f;
                    if (diag && col > row) s[nt][e] = -1e30f;
                }
            }
            // ---- online softmax (rows in quad: shfl 1,2) ----
            float mx0 = -1e30f, mx1 = -1e30f;
#pragma unroll
            for (int nt = 0; nt < 8; nt++) {
                mx0 = fmaxf(mx0, fmaxf(s[nt][0], s[nt][1]));
                mx1 = fmaxf(mx1, fmaxf(s[nt][2], s[nt][3]));
            }
            mx0 = fmaxf(mx0, __shfl_xor_sync(0xffffffffu, mx0, 1));
            mx0 = fmaxf(mx0, __shfl_xor_sync(0xffffffffu, mx0, 2));
            mx1 = fmaxf(mx1, __shfl_xor_sync(0xffffffffu, mx1, 1));
            mx1 = fmaxf(mx1, __shfl_xor_sync(0xffffffffu, mx1, 2));
            float mn0 = fmaxf(mr[0], mx0), mn1 = fmaxf(mr[1], mx1);
            float al0 = __expf(mr[0] - mn0), al1 = __expf(mr[1] - mn1);
            mr[0] = mn0; mr[1] = mn1;
            float sum0 = 0.f, sum1 = 0.f;
#pragma unroll
            for (int nt = 0; nt < 8; nt++) {
                s[nt][0] = __expf(s[nt][0] - mn0); sum0 += s[nt][0];
                s[nt][1] = __expf(s[nt][1] - mn0); sum0 += s[nt][1];
                s[nt][2] = __expf(s[nt][2] - mn1); sum1 += s[nt][2];
                s[nt][3] = __expf(s[nt][3] - mn1); sum1 += s[nt][3];
            }
            sum0 += __shfl_xor_sync(0xffffffffu, sum0, 1);
            sum0 += __shfl_xor_sync(0xffffffffu, sum0, 2);
            sum1 += __shfl_xor_sync(0xffffffffu, sum1, 1);
            sum1 += __shfl_xor_sync(0xffffffffu, sum1, 2);
            lr[0] = lr[0] * al0 + sum0;
            lr[1] = lr[1] * al1 + sum1;
#pragma unroll
            for (int nt = 0; nt < 8; nt++) {
                o[nt][0] *= al0; o[nt][1] *= al0;
                o[nt][2] *= al1; o[nt][3] *= al1;
            }
            // ---- O += P V : P packed straight from S C-frags ----
#pragma unroll
            for (int j = 0; j < 4; j++) {          // key group of 16
                uint32_t ap[4];
                ap[0] = packh2(s[2 * j][0],     s[2 * j][1]);
                ap[1] = packh2(s[2 * j][2],     s[2 * j][3]);
                ap[2] = packh2(s[2 * j + 1][0], s[2 * j + 1][1]);
                ap[3] = packh2(s[2 * j + 1][2], s[2 * j + 1][3]);
#pragma unroll
                for (int np = 0; np < 4; np++) {   // d group of 16
                    uint32_t bv[4];
                    ldm_x4_t(bv, vb + 2 * ((16 * j + v_row) * FSH + np * 16 + v_off));
                    mma_f16(o[2 * np],     ap, bv);
                    mma_f16(o[2 * np + 1], ap, bv + 2);
                }
            }
        }
    }

    // ---- normalize + store fp16 (A operand of proj GEMM) ----
    int b_ = bh >> 4, h = bh & 15;
    float i0 = 1.f / lr[0], i1 = 1.f / lr[1];
#pragma unroll
    for (int nt = 0; nt < 8; nt++) {
        int d = h * 64 + nt * 8 + 2 * t4;
        int r0 = qw + g, r1 = qw + 8 + g;
        *(uint32_t*)&out[(size_t)(b_ * SEQ + r0) * EMBD + d] = packh2(o[nt][0] * i0, o[nt][1] * i0);
        *(uint32_t*)&out[(size_t)(b_ * SEQ + r1) * EMBD + d] = packh2(o[nt][2] * i1, o[nt][3] * i1);
    }
}

// ---------------------------------------------------------------------------
extern "C" void kernel_launch(void* const* d_in, const int* in_sizes, int n_in,
                              void* d_out, int out_size)
{
    const float* x      = (const float*)d_in[0];
    const float* qkv_w  = (const float*)d_in[1];
    const float* qkv_b  = (const float*)d_in[2];
    const float* proj_w = (const float*)d_in[3];
    const float* proj_b = (const float*)d_in[4];

    float* out  = (float*)d_out;
    float* outK = out  + (size_t)BATCH * SEQ * EMBD;
    float* outV = outK + (size_t)BATCH * SEQ * EMBD;

    __half *qh, *kh, *vh, *ah, *xh, *wqh, *wph;
    cudaGetSymbolAddress((void**)&qh,  g_qh);
    cudaGetSymbolAddress((void**)&kh,  g_kh);
    cudaGetSymbolAddress((void**)&vh,  g_vh);
    cudaGetSymbolAddress((void**)&ah,  g_ah);
    cudaGetSymbolAddress((void**)&xh,  g_xh);
    cudaGetSymbolAddress((void**)&wqh, g_wqkvh);
    cudaGetSymbolAddress((void**)&wph, g_wprojh);

    const int gemm_smem  = 3 * 2 * 128 * GSH * (int)sizeof(__half);           // 110592
    const int flash_smem = (128 * FSH + 6 * 64 * FSH) * (int)sizeof(__half);  // 73728
    cudaFuncSetAttribute(gemm_tc,
                         cudaFuncAttributeMaxDynamicSharedMemorySize, gemm_smem);
    cudaFuncSetAttribute(flash_tc,
                         cudaFuncAttributeMaxDynamicSharedMemorySize, flash_smem);

    // 0) prep: convert x and transposed weights to fp16
    to_half_kernel<<<(M_TOTAL * EMBD / 8 + 255) / 256, 256>>>(x, xh, M_TOTAL * EMBD / 8);
    transpose_half_kernel<<<dim3(3 * EMBD / 32, EMBD / 32), dim3(32, 8)>>>(qkv_w, wqh, 3 * EMBD);
    transpose_half_kernel<<<dim3(EMBD / 32, EMBD / 32), dim3(32, 8)>>>(proj_w, wph, EMBD);

    // 1) QKV GEMM -> Q fp16; K,V fp32 canonical + fp16 scratch
    gemm_tc<<<dim3(3 * EMBD / 128, M_TOTAL / 128), 256, gemm_smem>>>(
        xh, wqh, qkv_b, 0, nullptr, outK, outV, qh, kh, vh);

    // 2) causal flash attention (fp16 tensor cores)
    flash_tc<<<dim3(SEQ / 128, BATCH * N_HEAD), 256, flash_smem>>>(
        qh, kh, vh, ah);

    // 3) output projection (fp16 in, fp32 out)
    gemm_tc<<<dim3(EMBD / 128, M_TOTAL / 128), 256, gemm_smem>>>(
        ah, wph, proj_b, 1, out, nullptr, nullptr, nullptr, nullptr, nullptr);
}

// round 8
// speedup vs baseline: 6.2522x; 1.0441x over previous
#include <cuda_runtime.h>
#include <cuda_fp16.h>
#include <math.h>
#include <stdint.h>

#define N_HEAD   16
#define HEAD_DIM 64
#define EMBD     1024
#define BATCH    2
#define SEQ      2048
#define M_TOTAL  (BATCH*SEQ)   // 4096

// ---------------- scratch (device globals; no allocs allowed) ---------------
__device__ __half g_qh[(size_t)BATCH*N_HEAD*SEQ*HEAD_DIM];   // Q fp16 [B,H,S,D]
__device__ __half g_kh[(size_t)BATCH*N_HEAD*SEQ*HEAD_DIM];   // K fp16 copy
__device__ __half g_vh[(size_t)BATCH*N_HEAD*SEQ*HEAD_DIM];   // V fp16 copy
__device__ __half g_ah[(size_t)M_TOTAL*EMBD];                // attn out fp16 [B*S,E]
__device__ __half g_xh[(size_t)M_TOTAL*EMBD];                // x fp16
__device__ __half g_wqkvh[(size_t)3*EMBD*EMBD];              // W_qkv^T fp16 [3072,1024]
__device__ __half g_wprojh[(size_t)EMBD*EMBD];               // W_proj^T fp16 [1024,1024]

// ---------------- helpers ---------------------------------------------------
__device__ __forceinline__ uint32_t smem_u32(const void* p) {
    uint32_t a;
    asm("{ .reg .u64 t; cvta.to.shared.u64 t, %1; cvt.u32.u64 %0, t; }" : "=r"(a) : "l"(p));
    return a;
}
__device__ __forceinline__ uint32_t packh2(float x, float y) {
    __half2 h = __floats2half2_rn(x, y);
    return *(uint32_t*)&h;
}
__device__ __forceinline__ void mma_f16(float* c, const uint32_t* a, const uint32_t* b) {
    asm volatile("mma.sync.aligned.m16n8k16.row.col.f32.f16.f16.f32 "
        "{%0,%1,%2,%3}, {%4,%5,%6,%7}, {%8,%9}, {%0,%1,%2,%3};"
        : "+f"(c[0]), "+f"(c[1]), "+f"(c[2]), "+f"(c[3])
        : "r"(a[0]), "r"(a[1]), "r"(a[2]), "r"(a[3]), "r"(b[0]), "r"(b[1]));
}
__device__ __forceinline__ void ldm_x4(uint32_t* r, uint32_t addr) {
    asm volatile("ldmatrix.sync.aligned.m8n8.x4.shared.b16 {%0,%1,%2,%3}, [%4];"
        : "=r"(r[0]), "=r"(r[1]), "=r"(r[2]), "=r"(r[3]) : "r"(addr));
}
__device__ __forceinline__ void ldm_x4_t(uint32_t* r, uint32_t addr) {
    asm volatile("ldmatrix.sync.aligned.m8n8.x4.trans.shared.b16 {%0,%1,%2,%3}, [%4];"
        : "=r"(r[0]), "=r"(r[1]), "=r"(r[2]), "=r"(r[3]) : "r"(addr));
}
__device__ __forceinline__ void cp16(void* dst_smem, const void* src) {
    uint32_t d = smem_u32(dst_smem);
    asm volatile("cp.async.cg.shared.global [%0], [%1], 16;" :: "r"(d), "l"(src) : "memory");
}
#define CP_COMMIT() asm volatile("cp.async.commit_group;" ::: "memory")
#define CP_WAIT(n)  asm volatile("cp.async.wait_group %0;" :: "n"(n) : "memory")

// ---------------- prep kernels ----------------------------------------------
__global__ __launch_bounds__(256)
void to_half_kernel(const float* __restrict__ x, __half* __restrict__ y, int n8)
{
    int i = blockIdx.x * blockDim.x + threadIdx.x;
    if (i < n8) {
        float4 a = ((const float4*)x)[2 * i];
        float4 b = ((const float4*)x)[2 * i + 1];
        uint4 o;
        o.x = packh2(a.x, a.y); o.y = packh2(a.z, a.w);
        o.z = packh2(b.x, b.y); o.w = packh2(b.z, b.w);
        ((uint4*)y)[i] = o;
    }
}

// Merged transpose of both weight matrices: blocks 0..95 -> qkv, 96..127 -> proj
__global__ __launch_bounds__(256)
void transpose_both_kernel(const float* __restrict__ Wq, const float* __restrict__ Wp,
                           __half* __restrict__ WTq, __half* __restrict__ WTp)
{
    __shared__ float t[32][33];
    bool is_q = blockIdx.x < 96;
    const float* W  = is_q ? Wq  : Wp;
    __half* WT      = is_q ? WTq : WTp;
    int N           = is_q ? 3 * EMBD : EMBD;
    int n0 = (is_q ? blockIdx.x : blockIdx.x - 96) * 32;
    int k0 = blockIdx.y * 32;
    int tx = threadIdx.x, ty = threadIdx.y;
#pragma unroll
    for (int i = 0; i < 4; i++)
        t[ty + 8 * i][tx] = W[(size_t)(k0 + ty + 8 * i) * N + n0 + tx];
    __syncthreads();
#pragma unroll
    for (int i = 0; i < 4; i++)
        WT[(size_t)(n0 + ty + 8 * i) * EMBD + k0 + tx] = __float2half(t[tx][ty + 8 * i]);
}

// ---------------- fp16 mma.sync GEMM ----------------------------------------
// C[M,Ntot] = A[M,1024] @ Bt^T + bias.  Block 128x128, BK=64, 3-stage cp.async,
// one barrier per K-tile, A-fragments register double-buffered across k16 steps.
#define GSH 72       // stride (halves) = 144B: 64 data + 8 pad; ldmatrix conflict-free
#define GKT (EMBD/64)

__global__ __launch_bounds__(256, 2)
void gemm_tc(const __half* __restrict__ A, const __half* __restrict__ Bt,
             const float* __restrict__ bias, int mode,
             float* __restrict__ o0, float* __restrict__ o1, float* __restrict__ o2,
             __half* __restrict__ h0, __half* __restrict__ h1, __half* __restrict__ h2)
{
    extern __shared__ __half smg[];
    __half* SA = smg;                      // [3][128*GSH]
    __half* SB = smg + 3 * 128 * GSH;      // [3][128*GSH]

    const int tid = threadIdx.x, wid = tid >> 5, lane = tid & 31;
    const int g = lane >> 2, t4 = lane & 3;
    const int wm = wid >> 1, wn = wid & 1;
    const int m0 = blockIdx.y * 128, n0 = blockIdx.x * 128;
    const __half* Ab = A  + (size_t)m0 * EMBD;
    const __half* Bb = Bt + (size_t)n0 * EMBD;

    float c[2][8][4];
#pragma unroll
    for (int mt = 0; mt < 2; mt++)
#pragma unroll
        for (int nt = 0; nt < 8; nt++)
#pragma unroll
            for (int e = 0; e < 4; e++) c[mt][nt][e] = 0.f;

    auto load_tile = [&](int t) {
        __half* as = SA + (t % 3) * 128 * GSH;
        __half* bs = SB + (t % 3) * 128 * GSH;
        int kt = t * 64;
#pragma unroll
        for (int i = 0; i < 4; i++) {
            int idx = tid + i * 256;
            int r = idx >> 3, ch = idx & 7;
            cp16(as + r * GSH + ch * 8, Ab + (size_t)r * EMBD + kt + ch * 8);
        }
#pragma unroll
        for (int i = 0; i < 4; i++) {
            int idx = tid + i * 256;
            int r = idx >> 3, ch = idx & 7;
            cp16(bs + r * GSH + ch * 8, Bb + (size_t)r * EMBD + kt + ch * 8);
        }
    };

    load_tile(0); CP_COMMIT();
    load_tile(1); CP_COMMIT();

    const int a_row = (lane & 15), a_off = (lane >> 4) * 8;
    const int b_row = ((lane >> 4) & 1) * 8 + (lane & 7), b_off = ((lane >> 3) & 1) * 8;

    for (int t = 0; t < GKT; t++) {
        CP_WAIT(1);            // tile t resident (t+1 may be in flight)
        __syncthreads();       // all warps done iter t-1 (buf (t+2)%3 writable)
        if (t + 2 < GKT) { load_tile(t + 2); CP_COMMIT(); }
        else             { CP_COMMIT(); }
        uint32_t sa = smem_u32(SA + (t % 3) * 128 * GSH);
        uint32_t sb = smem_u32(SB + (t % 3) * 128 * GSH);

        uint32_t aA[2][4], aB[2][4];
#pragma unroll
        for (int mt = 0; mt < 2; mt++)
            ldm_x4(aA[mt], sa + 2 * ((wm * 32 + mt * 16 + a_row) * GSH + a_off));
#pragma unroll
        for (int ks = 0; ks < 4; ks++) {
            int k0 = ks * 16;
            uint32_t b[4][4];
#pragma unroll
            for (int ng = 0; ng < 4; ng++)
                ldm_x4(b[ng], sb + 2 * ((wn * 64 + ng * 16 + b_row) * GSH + k0 + b_off));
            // prefetch next ks A frags into the alternate buffer
            if (ks < 3) {
#pragma unroll
                for (int mt = 0; mt < 2; mt++)
                    ldm_x4((ks & 1) ? aA[mt] : aB[mt],
                           sa + 2 * ((wm * 32 + mt * 16 + a_row) * GSH + k0 + 16 + a_off));
            }
#pragma unroll
            for (int mt = 0; mt < 2; mt++) {
                const uint32_t* cur = (ks & 1) ? aB[mt] : aA[mt];
#pragma unroll
                for (int ng = 0; ng < 4; ng++) {
                    mma_f16(c[mt][2 * ng],     cur, b[ng]);
                    mma_f16(c[mt][2 * ng + 1], cur, b[ng] + 2);
                }
            }
        }
    }

    // epilogue: c0,c1 = row g cols 2t4,2t4+1; c2,c3 = row g+8
#pragma unroll
    for (int mt = 0; mt < 2; mt++) {
#pragma unroll
        for (int nt = 0; nt < 8; nt++) {
            int row0 = m0 + wm * 32 + mt * 16 + g;
            int row1 = row0 + 8;
            int col  = n0 + wn * 64 + nt * 8 + 2 * t4;
            float b0 = bias[col], b1 = bias[col + 1];
            float2 v0 = make_float2(c[mt][nt][0] + b0, c[mt][nt][1] + b1);
            float2 v1 = make_float2(c[mt][nt][2] + b0, c[mt][nt][3] + b1);
            if (mode == 0) {
                int sec = col >> 10, nn = col & 1023;
                int h = nn >> 6, d = nn & 63;
                int b_0 = row0 >> 11, s_0 = row0 & 2047;
                int b_1 = row1 >> 11, s_1 = row1 & 2047;
                size_t i0 = (((size_t)(b_0 * N_HEAD + h) * SEQ + s_0) << 6) + d;
                size_t i1 = (((size_t)(b_1 * N_HEAD + h) * SEQ + s_1) << 6) + d;
                if (sec == 0) {
                    *(uint32_t*)&h0[i0] = packh2(v0.x, v0.y);
                    *(uint32_t*)&h0[i1] = packh2(v1.x, v1.y);
                } else if (sec == 1) {
                    *(float2*)&o1[i0] = v0;
                    *(float2*)&o1[i1] = v1;
                    *(uint32_t*)&h1[i0] = packh2(v0.x, v0.y);
                    *(uint32_t*)&h1[i1] = packh2(v1.x, v1.y);
                } else {
                    *(float2*)&o2[i0] = v0;
                    *(float2*)&o2[i1] = v1;
                    *(uint32_t*)&h2[i0] = packh2(v0.x, v0.y);
                    *(uint32_t*)&h2[i1] = packh2(v1.x, v1.y);
                }
            } else {
                *(float2*)&o0[(size_t)row0 * EMBD + col] = v0;
                *(float2*)&o0[(size_t)row1 * EMBD + col] = v1;
            }
        }
    }
}

// ---------------- flash attention (fp16 mma, 4-stage KV, paired subtiles) ----
// Block: 128 queries x one (b,h); 8 warps, warp = 16 rows x 64 cols.
// 4x64-row KV ring; ONE barrier + ONE cp.async wait per TWO subtiles
// (reuse distance 4). Q fragments hoisted into registers.
#define FSH 72

__global__ __launch_bounds__(256, 2)
void flash_tc(const __half* __restrict__ q, const __half* __restrict__ k,
              const __half* __restrict__ v, __half* __restrict__ out)
{
    extern __shared__ __half smf[];
    __half* Qs = smf;                    // [128][FSH]
    __half* Ks = smf + 128 * FSH;        // [4][64][FSH]
    __half* Vs = Ks + 4 * 64 * FSH;      // [4][64][FSH]

    const int tid = threadIdx.x, wid = tid >> 5, lane = tid & 31;
    const int g = lane >> 2, t4 = lane & 3;
    const int qb = gridDim.x - 1 - blockIdx.x;   // big causal blocks first
    const int bh = blockIdx.y;
    const int q0 = qb * 128;
    const size_t base = (size_t)bh * SEQ * HEAD_DIM;
    const int qw = q0 + wid * 16;
    const int jtmax = 2 * qb + 1;                // odd: subtiles come in pairs

    auto load_kv = [&](int j) {
        __half* kd = Ks + (j & 3) * 64 * FSH;
        __half* vd = Vs + (j & 3) * 64 * FSH;
        const __half* kg = k + base + (size_t)j * 64 * 64;
        const __half* vg = v + base + (size_t)j * 64 * 64;
#pragma unroll
        for (int i = 0; i < 2; i++) {
            int idx = tid + i * 256;
            int r = idx >> 3, ch = idx & 7;
            cp16(kd + r * FSH + ch * 8, kg + (size_t)r * 64 + ch * 8);
            cp16(vd + r * FSH + ch * 8, vg + (size_t)r * 64 + ch * 8);
        }
    };

    // prologue: Q + first two KV subtiles, one group
#pragma unroll
    for (int i = 0; i < 4; i++) {
        int idx = tid + i * 256;
        int r = idx >> 3, ch = idx & 7;
        cp16(Qs + r * FSH + ch * 8, q + base + (size_t)(q0 + r) * 64 + ch * 8);
    }
    load_kv(0);
    load_kv(1);
    CP_COMMIT();

    float mr[2] = {-1e30f, -1e30f}, lr[2] = {0.f, 0.f};
    float o[8][4];
#pragma unroll
    for (int nt = 0; nt < 8; nt++)
#pragma unroll
        for (int e = 0; e < 4; e++) o[nt][e] = 0.f;

    const int a_row = (lane & 15), a_off = (lane >> 4) * 8;
    const int b_row = ((lane >> 4) & 1) * 8 + (lane & 7), b_off = ((lane >> 3) & 1) * 8;
    const int v_row = ((lane >> 3) & 1) * 8 + (lane & 7), v_off = (lane >> 4) * 8;

    uint32_t aq[4][4];   // hoisted Q fragments, one per k16 step

    auto subtile = [&](int j) {
        if (j * 64 > qw + 15) return;        // fully masked for this warp
        uint32_t kb = smem_u32(Ks + (j & 3) * 64 * FSH);
        uint32_t vb = smem_u32(Vs + (j & 3) * 64 * FSH);

        // ---- S = Q K^T ----
        float s[8][4];
#pragma unroll
        for (int nt = 0; nt < 8; nt++)
#pragma unroll
            for (int e = 0; e < 4; e++) s[nt][e] = 0.f;
#pragma unroll
        for (int ks = 0; ks < 4; ks++) {
            int k0 = ks * 16;
            uint32_t bk[4][4];
#pragma unroll
            for (int ng = 0; ng < 4; ng++)
                ldm_x4(bk[ng], kb + 2 * ((ng * 16 + b_row) * FSH + k0 + b_off));
#pragma unroll
            for (int ng = 0; ng < 4; ng++) {
                mma_f16(s[2 * ng],     aq[ks], bk[ng]);
                mma_f16(s[2 * ng + 1], aq[ks], bk[ng] + 2);
            }
        }
        // ---- scale + causal mask ----
        bool diag = (j * 64 + 63 > qw);
#pragma unroll
        for (int nt = 0; nt < 8; nt++) {
            int colb = j * 64 + nt * 8 + 2 * t4;
#pragma unroll
            for (int e = 0; e < 4; e++) {
                int row = qw + g + (e >> 1) * 8;
                int col = colb + (e & 1);
                s[nt][e] *= 0.125f;
                if (diag && col > row) s[nt][e] = -1e30f;
            }
        }
        // ---- online softmax (rows live in a quad: shfl 1,2) ----
        float mx0 = -1e30f, mx1 = -1e30f;
#pragma unroll
        for (int nt = 0; nt < 8; nt++) {
            mx0 = fmaxf(mx0, fmaxf(s[nt][0], s[nt][1]));
            mx1 = fmaxf(mx1, fmaxf(s[nt][2], s[nt][3]));
        }
        mx0 = fmaxf(mx0, __shfl_xor_sync(0xffffffffu, mx0, 1));
        mx0 = fmaxf(mx0, __shfl_xor_sync(0xffffffffu, mx0, 2));
        mx1 = fmaxf(mx1, __shfl_xor_sync(0xffffffffu, mx1, 1));
        mx1 = fmaxf(mx1, __shfl_xor_sync(0xffffffffu, mx1, 2));
        float mn0 = fmaxf(mr[0], mx0), mn1 = fmaxf(mr[1], mx1);
        float al0 = __expf(mr[0] - mn0), al1 = __expf(mr[1] - mn1);
        mr[0] = mn0; mr[1] = mn1;
        float sum0 = 0.f, sum1 = 0.f;
#pragma unroll
        for (int nt = 0; nt < 8; nt++) {
            s[nt][0] = __expf(s[nt][0] - mn0); sum0 += s[nt][0];
            s[nt][1] = __expf(s[nt][1] - mn0); sum0 += s[nt][1];
            s[nt][2] = __expf(s[nt][2] - mn1); sum1 += s[nt][2];
            s[nt][3] = __expf(s[nt][3] - mn1); sum1 += s[nt][3];
        }
        sum0 += __shfl_xor_sync(0xffffffffu, sum0, 1);
        sum0 += __shfl_xor_sync(0xffffffffu, sum0, 2);
        sum1 += __shfl_xor_sync(0xffffffffu, sum1, 1);
        sum1 += __shfl_xor_sync(0xffffffffu, sum1, 2);
        lr[0] = lr[0] * al0 + sum0;
        lr[1] = lr[1] * al1 + sum1;
#pragma unroll
        for (int nt = 0; nt < 8; nt++) {
            o[nt][0] *= al0; o[nt][1] *= al0;
            o[nt][2] *= al1; o[nt][3] *= al1;
        }
        // ---- O += P V : P packed straight from S C-frags ----
#pragma unroll
        for (int jj = 0; jj < 4; jj++) {
            uint32_t ap[4];
            ap[0] = packh2(s[2 * jj][0],     s[2 * jj][1]);
            ap[1] = packh2(s[2 * jj][2],     s[2 * jj][3]);
            ap[2] = packh2(s[2 * jj + 1][0], s[2 * jj + 1][1]);
            ap[3] = packh2(s[2 * jj + 1][2], s[2 * jj + 1][3]);
#pragma unroll
            for (int np = 0; np < 4; np++) {
                uint32_t bv[4];
                ldm_x4_t(bv, vb + 2 * ((16 * jj + v_row) * FSH + np * 16 + v_off));
                mma_f16(o[2 * np],     ap, bv);
                mma_f16(o[2 * np + 1], ap, bv + 2);
            }
        }
    };

    for (int tp = 0; tp <= jtmax; tp += 2) {
        CP_WAIT(0);            // everything issued so far (incl. tiles tp, tp+1)
        __syncthreads();       // all warps done pair tp-2 -> stages (tp+2)&3,(tp+3)&3 free
        if (tp == 0) {         // Q resident now: hoist fragments
#pragma unroll
            for (int ks = 0; ks < 4; ks++)
                ldm_x4(aq[ks], smem_u32(Qs) + 2 * ((wid * 16 + a_row) * FSH + ks * 16 + a_off));
        }
        if (tp + 2 <= jtmax) load_kv(tp + 2);
        if (tp + 3 <= jtmax) load_kv(tp + 3);
        CP_COMMIT();
        subtile(tp);
        subtile(tp + 1);
    }

    // ---- normalize + store fp16 (A operand of proj GEMM) ----
    int b_ = bh >> 4, h = bh & 15;
    float i0 = 1.f / lr[0], i1 = 1.f / lr[1];
#pragma unroll
    for (int nt = 0; nt < 8; nt++) {
        int d = h * 64 + nt * 8 + 2 * t4;
        int r0 = qw + g, r1 = qw + 8 + g;
        *(uint32_t*)&out[(size_t)(b_ * SEQ + r0) * EMBD + d] = packh2(o[nt][0] * i0, o[nt][1] * i0);
        *(uint32_t*)&out[(size_t)(b_ * SEQ + r1) * EMBD + d] = packh2(o[nt][2] * i1, o[nt][3] * i1);
    }
}

// ---------------------------------------------------------------------------
extern "C" void kernel_launch(void* const* d_in, const int* in_sizes, int n_in,
                              void* d_out, int out_size)
{
    const float* x      = (const float*)d_in[0];
    const float* qkv_w  = (const float*)d_in[1];
    const float* qkv_b  = (const float*)d_in[2];
    const float* proj_w = (const float*)d_in[3];
    const float* proj_b = (const float*)d_in[4];

    float* out  = (float*)d_out;
    float* outK = out  + (size_t)BATCH * SEQ * EMBD;
    float* outV = outK + (size_t)BATCH * SEQ * EMBD;

    __half *qh, *kh, *vh, *ah, *xh, *wqh, *wph;
    cudaGetSymbolAddress((void**)&qh,  g_qh);
    cudaGetSymbolAddress((void**)&kh,  g_kh);
    cudaGetSymbolAddress((void**)&vh,  g_vh);
    cudaGetSymbolAddress((void**)&ah,  g_ah);
    cudaGetSymbolAddress((void**)&xh,  g_xh);
    cudaGetSymbolAddress((void**)&wqh, g_wqkvh);
    cudaGetSymbolAddress((void**)&wph, g_wprojh);

    const int gemm_smem  = 3 * 2 * 128 * GSH * (int)sizeof(__half);           // 110592
    const int flash_smem = (128 * FSH + 8 * 64 * FSH) * (int)sizeof(__half);  // 92160
    cudaFuncSetAttribute(gemm_tc,
                         cudaFuncAttributeMaxDynamicSharedMemorySize, gemm_smem);
    cudaFuncSetAttribute(flash_tc,
                         cudaFuncAttributeMaxDynamicSharedMemorySize, flash_smem);

    // 0) prep: convert x to fp16; transpose both weight matrices (one launch)
    to_half_kernel<<<(M_TOTAL * EMBD / 8 + 255) / 256, 256>>>(x, xh, M_TOTAL * EMBD / 8);
    transpose_both_kernel<<<dim3(128, EMBD / 32), dim3(32, 8)>>>(qkv_w, proj_w, wqh, wph);

    // 1) QKV GEMM -> Q fp16; K,V fp32 canonical + fp16 scratch
    gemm_tc<<<dim3(3 * EMBD / 128, M_TOTAL / 128), 256, gemm_smem>>>(
        xh, wqh, qkv_b, 0, nullptr, outK, outV, qh, kh, vh);

    // 2) causal flash attention (fp16 tensor cores)
    flash_tc<<<dim3(SEQ / 128, BATCH * N_HEAD), 256, flash_smem>>>(
        qh, kh, vh, ah);

    // 3) output projection (fp16 in, fp32 out)
    gemm_tc<<<dim3(EMBD / 128, M_TOTAL / 128), 256, gemm_smem>>>(
        ah, wph, proj_b, 1, out, nullptr, nullptr, nullptr, nullptr, nullptr);
}

// round 9
// speedup vs baseline: 6.4534x; 1.0322x over previous
#include <cuda_runtime.h>
#include <cuda_fp16.h>
#include <math.h>
#include <stdint.h>

#define N_HEAD   16
#define HEAD_DIM 64
#define EMBD     1024
#define BATCH    2
#define SEQ      2048
#define M_TOTAL  (BATCH*SEQ)   // 4096

// Q is pre-scaled by 1/sqrt(64) * log2(e) so flash softmax runs in log2 domain.
#define QSC 0.1803368801111204f

// ---------------- scratch (device globals; no allocs allowed) ---------------
__device__ __half g_qh[(size_t)BATCH*N_HEAD*SEQ*HEAD_DIM];   // Q fp16 (pre-scaled)
__device__ __half g_kh[(size_t)BATCH*N_HEAD*SEQ*HEAD_DIM];   // K fp16 copy
__device__ __half g_vh[(size_t)BATCH*N_HEAD*SEQ*HEAD_DIM];   // V fp16 copy
__device__ __half g_ah[(size_t)M_TOTAL*EMBD];                // attn out fp16 [B*S,E]
__device__ __half g_xh[(size_t)M_TOTAL*EMBD];                // x fp16
__device__ __half g_wqkvh[(size_t)3*EMBD*EMBD];              // W_qkv^T fp16 [3072,1024]
__device__ __half g_wprojh[(size_t)EMBD*EMBD];               // W_proj^T fp16 [1024,1024]

// ---------------- helpers ---------------------------------------------------
__device__ __forceinline__ uint32_t smem_u32(const void* p) {
    uint32_t a;
    asm("{ .reg .u64 t; cvta.to.shared.u64 t, %1; cvt.u32.u64 %0, t; }" : "=r"(a) : "l"(p));
    return a;
}
__device__ __forceinline__ uint32_t packh2(float x, float y) {
    __half2 h = __floats2half2_rn(x, y);
    return *(uint32_t*)&h;
}
__device__ __forceinline__ float ex2f(float x) {
    float y;
    asm("ex2.approx.f32 %0, %1;" : "=f"(y) : "f"(x));
    return y;
}
__device__ __forceinline__ void mma_f16(float* c, const uint32_t* a, const uint32_t* b) {
    asm volatile("mma.sync.aligned.m16n8k16.row.col.f32.f16.f16.f32 "
        "{%0,%1,%2,%3}, {%4,%5,%6,%7}, {%8,%9}, {%0,%1,%2,%3};"
        : "+f"(c[0]), "+f"(c[1]), "+f"(c[2]), "+f"(c[3])
        : "r"(a[0]), "r"(a[1]), "r"(a[2]), "r"(a[3]), "r"(b[0]), "r"(b[1]));
}
__device__ __forceinline__ void ldm_x4(uint32_t* r, uint32_t addr) {
    asm volatile("ldmatrix.sync.aligned.m8n8.x4.shared.b16 {%0,%1,%2,%3}, [%4];"
        : "=r"(r[0]), "=r"(r[1]), "=r"(r[2]), "=r"(r[3]) : "r"(addr));
}
__device__ __forceinline__ void ldm_x4_t(uint32_t* r, uint32_t addr) {
    asm volatile("ldmatrix.sync.aligned.m8n8.x4.trans.shared.b16 {%0,%1,%2,%3}, [%4];"
        : "=r"(r[0]), "=r"(r[1]), "=r"(r[2]), "=r"(r[3]) : "r"(addr));
}
__device__ __forceinline__ void cp16(void* dst_smem, const void* src) {
    uint32_t d = smem_u32(dst_smem);
    asm volatile("cp.async.cg.shared.global [%0], [%1], 16;" :: "r"(d), "l"(src) : "memory");
}
#define CP_COMMIT() asm volatile("cp.async.commit_group;" ::: "memory")
#define CP_WAIT(n)  asm volatile("cp.async.wait_group %0;" :: "n"(n) : "memory")

// ---------------- prep kernels ----------------------------------------------
__global__ __launch_bounds__(256)
void to_half_kernel(const float* __restrict__ x, __half* __restrict__ y, int n8)
{
    int i = blockIdx.x * blockDim.x + threadIdx.x;
    if (i < n8) {
        float4 a = ((const float4*)x)[2 * i];
        float4 b = ((const float4*)x)[2 * i + 1];
        uint4 o;
        o.x = packh2(a.x, a.y); o.y = packh2(a.z, a.w);
        o.z = packh2(b.x, b.y); o.w = packh2(b.z, b.w);
        ((uint4*)y)[i] = o;
    }
}

// Merged transpose of both weight matrices: blocks 0..95 -> qkv, 96..127 -> proj
__global__ __launch_bounds__(256)
void transpose_both_kernel(const float* __restrict__ Wq, const float* __restrict__ Wp,
                           __half* __restrict__ WTq, __half* __restrict__ WTp)
{
    __shared__ float t[32][33];
    bool is_q = blockIdx.x < 96;
    const float* W  = is_q ? Wq  : Wp;
    __half* WT      = is_q ? WTq : WTp;
    int N           = is_q ? 3 * EMBD : EMBD;
    int n0 = (is_q ? blockIdx.x : blockIdx.x - 96) * 32;
    int k0 = blockIdx.y * 32;
    int tx = threadIdx.x, ty = threadIdx.y;
#pragma unroll
    for (int i = 0; i < 4; i++)
        t[ty + 8 * i][tx] = W[(size_t)(k0 + ty + 8 * i) * N + n0 + tx];
    __syncthreads();
#pragma unroll
    for (int i = 0; i < 4; i++)
        WT[(size_t)(n0 + ty + 8 * i) * EMBD + k0 + tx] = __float2half(t[tx][ty + 8 * i]);
}

// ---------------- fp16 mma.sync GEMM ----------------------------------------
// C[M,Ntot] = A[M,1024] @ Bt^T + bias.  Block 128x128, BK=64, 3-stage cp.async,
// one barrier per K-tile, A-fragments register double-buffered across k16 steps.
#define GSH 72       // stride (halves) = 144B: 64 data + 8 pad; ldmatrix conflict-free
#define GKT (EMBD/64)

__global__ __launch_bounds__(256, 2)
void gemm_tc(const __half* __restrict__ A, const __half* __restrict__ Bt,
             const float* __restrict__ bias, int mode,
             float* __restrict__ o0, float* __restrict__ o1, float* __restrict__ o2,
             __half* __restrict__ h0, __half* __restrict__ h1, __half* __restrict__ h2)
{
    extern __shared__ __half smg[];
    __half* SA = smg;                      // [3][128*GSH]
    __half* SB = smg + 3 * 128 * GSH;      // [3][128*GSH]

    const int tid = threadIdx.x, wid = tid >> 5, lane = tid & 31;
    const int g = lane >> 2, t4 = lane & 3;
    const int wm = wid >> 1, wn = wid & 1;
    const int m0 = blockIdx.y * 128, n0 = blockIdx.x * 128;
    const __half* Ab = A  + (size_t)m0 * EMBD;
    const __half* Bb = Bt + (size_t)n0 * EMBD;

    float c[2][8][4];
#pragma unroll
    for (int mt = 0; mt < 2; mt++)
#pragma unroll
        for (int nt = 0; nt < 8; nt++)
#pragma unroll
            for (int e = 0; e < 4; e++) c[mt][nt][e] = 0.f;

    auto load_tile = [&](int t) {
        __half* as = SA + (t % 3) * 128 * GSH;
        __half* bs = SB + (t % 3) * 128 * GSH;
        int kt = t * 64;
#pragma unroll
        for (int i = 0; i < 4; i++) {
            int idx = tid + i * 256;
            int r = idx >> 3, ch = idx & 7;
            cp16(as + r * GSH + ch * 8, Ab + (size_t)r * EMBD + kt + ch * 8);
        }
#pragma unroll
        for (int i = 0; i < 4; i++) {
            int idx = tid + i * 256;
            int r = idx >> 3, ch = idx & 7;
            cp16(bs + r * GSH + ch * 8, Bb + (size_t)r * EMBD + kt + ch * 8);
        }
    };

    load_tile(0); CP_COMMIT();
    load_tile(1); CP_COMMIT();

    const int a_row = (lane & 15), a_off = (lane >> 4) * 8;
    const int b_row = ((lane >> 4) & 1) * 8 + (lane & 7), b_off = ((lane >> 3) & 1) * 8;

    for (int t = 0; t < GKT; t++) {
        CP_WAIT(1);            // tile t resident (t+1 may be in flight)
        __syncthreads();       // all warps done iter t-1 (buf (t+2)%3 writable)
        if (t + 2 < GKT) { load_tile(t + 2); CP_COMMIT(); }
        else             { CP_COMMIT(); }
        uint32_t sa = smem_u32(SA + (t % 3) * 128 * GSH);
        uint32_t sb = smem_u32(SB + (t % 3) * 128 * GSH);

        uint32_t aA[2][4], aB[2][4];
#pragma unroll
        for (int mt = 0; mt < 2; mt++)
            ldm_x4(aA[mt], sa + 2 * ((wm * 32 + mt * 16 + a_row) * GSH + a_off));
#pragma unroll
        for (int ks = 0; ks < 4; ks++) {
            int k0 = ks * 16;
            uint32_t b[4][4];
#pragma unroll
            for (int ng = 0; ng < 4; ng++)
                ldm_x4(b[ng], sb + 2 * ((wn * 64 + ng * 16 + b_row) * GSH + k0 + b_off));
            if (ks < 3) {
#pragma unroll
                for (int mt = 0; mt < 2; mt++)
                    ldm_x4((ks & 1) ? aA[mt] : aB[mt],
                           sa + 2 * ((wm * 32 + mt * 16 + a_row) * GSH + k0 + 16 + a_off));
            }
#pragma unroll
            for (int mt = 0; mt < 2; mt++) {
                const uint32_t* cur = (ks & 1) ? aB[mt] : aA[mt];
#pragma unroll
                for (int ng = 0; ng < 4; ng++) {
                    mma_f16(c[mt][2 * ng],     cur, b[ng]);
                    mma_f16(c[mt][2 * ng + 1], cur, b[ng] + 2);
                }
            }
        }
    }

    // epilogue: c0,c1 = row g cols 2t4,2t4+1; c2,c3 = row g+8
#pragma unroll
    for (int mt = 0; mt < 2; mt++) {
#pragma unroll
        for (int nt = 0; nt < 8; nt++) {
            int row0 = m0 + wm * 32 + mt * 16 + g;
            int row1 = row0 + 8;
            int col  = n0 + wn * 64 + nt * 8 + 2 * t4;
            float b0 = bias[col], b1 = bias[col + 1];
            float2 v0 = make_float2(c[mt][nt][0] + b0, c[mt][nt][1] + b1);
            float2 v1 = make_float2(c[mt][nt][2] + b0, c[mt][nt][3] + b1);
            if (mode == 0) {
                int sec = col >> 10, nn = col & 1023;
                int h = nn >> 6, d = nn & 63;
                int b_0 = row0 >> 11, s_0 = row0 & 2047;
                int b_1 = row1 >> 11, s_1 = row1 & 2047;
                size_t i0 = (((size_t)(b_0 * N_HEAD + h) * SEQ + s_0) << 6) + d;
                size_t i1 = (((size_t)(b_1 * N_HEAD + h) * SEQ + s_1) << 6) + d;
                if (sec == 0) {           // Q: fp16 scratch, pre-scaled for softmax
                    *(uint32_t*)&h0[i0] = packh2(v0.x * QSC, v0.y * QSC);
                    *(uint32_t*)&h0[i1] = packh2(v1.x * QSC, v1.y * QSC);
                } else if (sec == 1) {    // K: fp32 canonical + fp16 scratch
                    *(float2*)&o1[i0] = v0;
                    *(float2*)&o1[i1] = v1;
                    *(uint32_t*)&h1[i0] = packh2(v0.x, v0.y);
                    *(uint32_t*)&h1[i1] = packh2(v1.x, v1.y);
                } else {                  // V: fp32 canonical + fp16 scratch
                    *(float2*)&o2[i0] = v0;
                    *(float2*)&o2[i1] = v1;
                    *(uint32_t*)&h2[i0] = packh2(v0.x, v0.y);
                    *(uint32_t*)&h2[i1] = packh2(v1.x, v1.y);
                }
            } else {
                *(float2*)&o0[(size_t)row0 * EMBD + col] = v0;
                *(float2*)&o0[(size_t)row1 * EMBD + col] = v1;
            }
        }
    }
}

// ---------------- flash attention (fp16 mma, log2-domain softmax) ------------
// Block: 128 queries x one (b,h); 8 warps, warp = 16 rows x 64 cols.
// 4x64-row KV ring, one barrier per TWO subtiles. Q fragments hoisted.
// Q pre-scaled by 0.125*log2e -> p = ex2(s - mn), no scale/mul-by-log2e ops.
#define FSH 72

__global__ __launch_bounds__(256, 2)
void flash_tc(const __half* __restrict__ q, const __half* __restrict__ k,
              const __half* __restrict__ v, __half* __restrict__ out)
{
    extern __shared__ __half smf[];
    __half* Qs = smf;                    // [128][FSH]
    __half* Ks = smf + 128 * FSH;        // [4][64][FSH]
    __half* Vs = Ks + 4 * 64 * FSH;      // [4][64][FSH]

    const int tid = threadIdx.x, wid = tid >> 5, lane = tid & 31;
    const int g = lane >> 2, t4 = lane & 3;
    const int qb = gridDim.x - 1 - blockIdx.x;   // big causal blocks first
    const int bh = blockIdx.y;
    const int q0 = qb * 128;
    const size_t base = (size_t)bh * SEQ * HEAD_DIM;
    const int qw = q0 + wid * 16;
    const int jtmax = 2 * qb + 1;                // odd: subtiles come in pairs

    auto load_kv = [&](int j) {
        __half* kd = Ks + (j & 3) * 64 * FSH;
        __half* vd = Vs + (j & 3) * 64 * FSH;
        const __half* kg = k + base + (size_t)j * 64 * 64;
        const __half* vg = v + base + (size_t)j * 64 * 64;
#pragma unroll
        for (int i = 0; i < 2; i++) {
            int idx = tid + i * 256;
            int r = idx >> 3, ch = idx & 7;
            cp16(kd + r * FSH + ch * 8, kg + (size_t)r * 64 + ch * 8);
            cp16(vd + r * FSH + ch * 8, vg + (size_t)r * 64 + ch * 8);
        }
    };

    // prologue: Q + first two KV subtiles, one group
#pragma unroll
    for (int i = 0; i < 4; i++) {
        int idx = tid + i * 256;
        int r = idx >> 3, ch = idx & 7;
        cp16(Qs + r * FSH + ch * 8, q + base + (size_t)(q0 + r) * 64 + ch * 8);
    }
    load_kv(0);
    load_kv(1);
    CP_COMMIT();

    float mr[2] = {-1e30f, -1e30f}, lr[2] = {0.f, 0.f};
    float o[8][4];
#pragma unroll
    for (int nt = 0; nt < 8; nt++)
#pragma unroll
        for (int e = 0; e < 4; e++) o[nt][e] = 0.f;

    const int a_row = (lane & 15), a_off = (lane >> 4) * 8;
    const int b_row = ((lane >> 4) & 1) * 8 + (lane & 7), b_off = ((lane >> 3) & 1) * 8;
    const int v_row = ((lane >> 3) & 1) * 8 + (lane & 7), v_off = (lane >> 4) * 8;

    uint32_t aq[4][4];   // hoisted Q fragments, one per k16 step

    auto subtile = [&](int j) {
        if (j * 64 > qw + 15) return;        // fully masked for this warp
        uint32_t kb = smem_u32(Ks + (j & 3) * 64 * FSH);
        uint32_t vb = smem_u32(Vs + (j & 3) * 64 * FSH);

        // ---- S = Q K^T (already in log2 softmax domain) ----
        float s[8][4];
#pragma unroll
        for (int nt = 0; nt < 8; nt++)
#pragma unroll
            for (int e = 0; e < 4; e++) s[nt][e] = 0.f;
#pragma unroll
        for (int ks = 0; ks < 4; ks++) {
            int k0 = ks * 16;
            uint32_t bk[4][4];
#pragma unroll
            for (int ng = 0; ng < 4; ng++)
                ldm_x4(bk[ng], kb + 2 * ((ng * 16 + b_row) * FSH + k0 + b_off));
#pragma unroll
            for (int ng = 0; ng < 4; ng++) {
                mma_f16(s[2 * ng],     aq[ks], bk[ng]);
                mma_f16(s[2 * ng + 1], aq[ks], bk[ng] + 2);
            }
        }
        // ---- causal mask: only the diagonal subtile needs it ----
        if (j * 64 + 63 > qw) {
#pragma unroll
            for (int nt = 0; nt < 8; nt++) {
                int colb = j * 64 + nt * 8 + 2 * t4;
#pragma unroll
                for (int e = 0; e < 4; e++) {
                    int row = qw + g + (e >> 1) * 8;
                    int col = colb + (e & 1);
                    if (col > row) s[nt][e] = -1e30f;
                }
            }
        }
        // ---- online softmax in log2 domain (rows live in quad: shfl 1,2) ----
        float mx0 = -1e30f, mx1 = -1e30f;
#pragma unroll
        for (int nt = 0; nt < 8; nt++) {
            mx0 = fmaxf(mx0, fmaxf(s[nt][0], s[nt][1]));
            mx1 = fmaxf(mx1, fmaxf(s[nt][2], s[nt][3]));
        }
        mx0 = fmaxf(mx0, __shfl_xor_sync(0xffffffffu, mx0, 1));
        mx0 = fmaxf(mx0, __shfl_xor_sync(0xffffffffu, mx0, 2));
        mx1 = fmaxf(mx1, __shfl_xor_sync(0xffffffffu, mx1, 1));
        mx1 = fmaxf(mx1, __shfl_xor_sync(0xffffffffu, mx1, 2));
        float mn0 = fmaxf(mr[0], mx0), mn1 = fmaxf(mr[1], mx1);
        float al0 = ex2f(mr[0] - mn0), al1 = ex2f(mr[1] - mn1);
        mr[0] = mn0; mr[1] = mn1;
        float sum0 = 0.f, sum1 = 0.f;
#pragma unroll
        for (int nt = 0; nt < 8; nt++) {
            s[nt][0] = ex2f(s[nt][0] - mn0); sum0 += s[nt][0];
            s[nt][1] = ex2f(s[nt][1] - mn0); sum0 += s[nt][1];
            s[nt][2] = ex2f(s[nt][2] - mn1); sum1 += s[nt][2];
            s[nt][3] = ex2f(s[nt][3] - mn1); sum1 += s[nt][3];
        }
        sum0 += __shfl_xor_sync(0xffffffffu, sum0, 1);
        sum0 += __shfl_xor_sync(0xffffffffu, sum0, 2);
        sum1 += __shfl_xor_sync(0xffffffffu, sum1, 1);
        sum1 += __shfl_xor_sync(0xffffffffu, sum1, 2);
        lr[0] = lr[0] * al0 + sum0;
        lr[1] = lr[1] * al1 + sum1;
#pragma unroll
        for (int nt = 0; nt < 8; nt++) {
            o[nt][0] *= al0; o[nt][1] *= al0;
            o[nt][2] *= al1; o[nt][3] *= al1;
        }
        // ---- O += P V : P packed straight from S C-frags ----
#pragma unroll
        for (int jj = 0; jj < 4; jj++) {
            uint32_t ap[4];
            ap[0] = packh2(s[2 * jj][0],     s[2 * jj][1]);
            ap[1] = packh2(s[2 * jj][2],     s[2 * jj][3]);
            ap[2] = packh2(s[2 * jj + 1][0], s[2 * jj + 1][1]);
            ap[3] = packh2(s[2 * jj + 1][2], s[2 * jj + 1][3]);
#pragma unroll
            for (int np = 0; np < 4; np++) {
                uint32_t bv[4];
                ldm_x4_t(bv, vb + 2 * ((16 * jj + v_row) * FSH + np * 16 + v_off));
                mma_f16(o[2 * np],     ap, bv);
                mma_f16(o[2 * np + 1], ap, bv + 2);
            }
        }
    };

    for (int tp = 0; tp <= jtmax; tp += 2) {
        CP_WAIT(0);            // tiles tp, tp+1 resident
        __syncthreads();       // all warps done pair tp-2 -> stages (tp+2)&3,(tp+3)&3 free
        if (tp == 0) {         // Q resident now: hoist fragments
#pragma unroll
            for (int ks = 0; ks < 4; ks++)
                ldm_x4(aq[ks], smem_u32(Qs) + 2 * ((wid * 16 + a_row) * FSH + ks * 16 + a_off));
        }
        if (tp + 2 <= jtmax) load_kv(tp + 2);
        if (tp + 3 <= jtmax) load_kv(tp + 3);
        CP_COMMIT();
        subtile(tp);
        subtile(tp + 1);
    }

    // ---- normalize + store fp16 (A operand of proj GEMM) ----
    int b_ = bh >> 4, h = bh & 15;
    float i0 = 1.f / lr[0], i1 = 1.f / lr[1];
#pragma unroll
    for (int nt = 0; nt < 8; nt++) {
        int d = h * 64 + nt * 8 + 2 * t4;
        int r0 = qw + g, r1 = qw + 8 + g;
        *(uint32_t*)&out[(size_t)(b_ * SEQ + r0) * EMBD + d] = packh2(o[nt][0] * i0, o[nt][1] * i0);
        *(uint32_t*)&out[(size_t)(b_ * SEQ + r1) * EMBD + d] = packh2(o[nt][2] * i1, o[nt][3] * i1);
    }
}

// ---------------------------------------------------------------------------
extern "C" void kernel_launch(void* const* d_in, const int* in_sizes, int n_in,
                              void* d_out, int out_size)
{
    const float* x      = (const float*)d_in[0];
    const float* qkv_w  = (const float*)d_in[1];
    const float* qkv_b  = (const float*)d_in[2];
    const float* proj_w = (const float*)d_in[3];
    const float* proj_b = (const float*)d_in[4];

    float* out  = (float*)d_out;
    float* outK = out  + (size_t)BATCH * SEQ * EMBD;
    float* outV = outK + (size_t)BATCH * SEQ * EMBD;

    __half *qh, *kh, *vh, *ah, *xh, *wqh, *wph;
    cudaGetSymbolAddress((void**)&qh,  g_qh);
    cudaGetSymbolAddress((void**)&kh,  g_kh);
    cudaGetSymbolAddress((void**)&vh,  g_vh);
    cudaGetSymbolAddress((void**)&ah,  g_ah);
    cudaGetSymbolAddress((void**)&xh,  g_xh);
    cudaGetSymbolAddress((void**)&wqh, g_wqkvh);
    cudaGetSymbolAddress((void**)&wph, g_wprojh);

    const int gemm_smem  = 3 * 2 * 128 * GSH * (int)sizeof(__half);           // 110592
    const int flash_smem = (128 * FSH + 8 * 64 * FSH) * (int)sizeof(__half);  // 92160
    cudaFuncSetAttribute(gemm_tc,
                         cudaFuncAttributeMaxDynamicSharedMemorySize, gemm_smem);
    cudaFuncSetAttribute(flash_tc,
                         cudaFuncAttributeMaxDynamicSharedMemorySize, flash_smem);

    // 0) prep: convert x to fp16; transpose both weight matrices (one launch)
    to_half_kernel<<<(M_TOTAL * EMBD / 8 + 255) / 256, 256>>>(x, xh, M_TOTAL * EMBD / 8);
    transpose_both_kernel<<<dim3(128, EMBD / 32), dim3(32, 8)>>>(qkv_w, proj_w, wqh, wph);

    // 1) QKV GEMM -> Q fp16 (pre-scaled); K,V fp32 canonical + fp16 scratch
    gemm_tc<<<dim3(3 * EMBD / 128, M_TOTAL / 128), 256, gemm_smem>>>(
        xh, wqh, qkv_b, 0, nullptr, outK, outV, qh, kh, vh);

    // 2) causal flash attention (fp16 tensor cores, log2-domain softmax)
    flash_tc<<<dim3(SEQ / 128, BATCH * N_HEAD), 256, flash_smem>>>(
        qh, kh, vh, ah);

    // 3) output projection (fp16 in, fp32 out)
    gemm_tc<<<dim3(EMBD / 128, M_TOTAL / 128), 256, gemm_smem>>>(
        ah, wph, proj_b, 1, out, nullptr, nullptr, nullptr, nullptr, nullptr);
}